// round 11
// baseline (speedup 1.0000x reference)
#include <cuda_runtime.h>
#include <cuda_fp16.h>
#include <cstdint>

#define NN   100000
#define NE   1600000
#define DIN  512
#define HD   128
#define DOUT 64

// ---------------- scratch (device globals: allocation-free) ----------------
__device__ float g_deg[NN];                     // dinv
__device__ float g_h0 [(size_t)NN * HD];
__device__ float g_h  [(size_t)NN * HD];
// combined residual input for conv GEMMs, pre-split fp16
__device__ __half g_comb_hi[(size_t)NN * HD];
__device__ __half g_comb_lo[(size_t)NN * HD];
// CSR build
__device__ int g_cnt[NN];
__device__ int g_rp [NN + 1];
__device__ int g_cur[NN];
__device__ int g_csr[NE];
__device__ int g_bsum[128], g_boff[128];
// K-major, fp16-split weights: [N][K]
__device__ __half g_w1t_hi[HD * DIN],    g_w1t_lo[HD * DIN];
__device__ __half g_cwt_hi[2 * HD * HD], g_cwt_lo[2 * HD * HD];
__device__ __half g_w2t_hi[DOUT * HD],   g_w2t_lo[DOUT * HD];

// ======================= helpers =====================
__device__ __forceinline__ uint32_t smem_to_u32(const void* p) {
    uint32_t a;
    asm("{ .reg .u64 t; cvta.to.shared.u64 t, %1; cvt.u32.u64 %0, t; }" : "=r"(a) : "l"(p));
    return a;
}
__device__ __forceinline__ void ldsm4(uint32_t* r, uint32_t addr) {
    asm volatile("ldmatrix.sync.aligned.m8n8.x4.shared.b16 {%0,%1,%2,%3}, [%4];"
                 : "=r"(r[0]), "=r"(r[1]), "=r"(r[2]), "=r"(r[3]) : "r"(addr));
}
__device__ __forceinline__ void mma_f16(float* c, const uint32_t* a, const uint32_t* b) {
    asm volatile("mma.sync.aligned.m16n8k16.row.col.f32.f16.f16.f32 "
                 "{%0,%1,%2,%3}, {%4,%5,%6,%7}, {%8,%9}, {%0,%1,%2,%3};"
                 : "+f"(c[0]), "+f"(c[1]), "+f"(c[2]), "+f"(c[3])
                 : "r"(a[0]), "r"(a[1]), "r"(a[2]), "r"(a[3]), "r"(b[0]), "r"(b[1]));
}
__device__ __forceinline__ void cp_async16(uint32_t dst, const void* src) {
    asm volatile("cp.async.cg.shared.global [%0], [%1], 16;"
                 :: "r"(dst), "l"((unsigned long long)__cvta_generic_to_global(src)) : "memory");
}
__device__ __forceinline__ void cp_commit() {
    asm volatile("cp.async.commit_group;" ::: "memory");
}
template<int N> __device__ __forceinline__ void cp_wait() {
    asm volatile("cp.async.wait_group %0;" :: "n"(N) : "memory");
}
__device__ __forceinline__ void split_f16(float x, __half& hi, __half& lo) {
    hi = __float2half_rn(x);
    lo = __float2half_rn(x - __half2float(hi));
}

// ---------------- CSR build ----------------
__global__ void cnt_init_kernel() {
    int i = blockIdx.x * blockDim.x + threadIdx.x;
    if (i < NN) g_cnt[i] = 0;
}
__global__ void cnt_accum_kernel(const int* __restrict__ ei) {
    int e = blockIdx.x * blockDim.x + threadIdx.x;
    if (e < NE) atomicAdd(&g_cnt[ei[NE + e]], 1);
}
__global__ void scan1_kernel() {      // 98 blocks x 1024
    __shared__ int s[1024];
    int t = threadIdx.x;
    int i = blockIdx.x * 1024 + t;
    int x = (i < NN) ? g_cnt[i] : 0;
    s[t] = x;
    __syncthreads();
    #pragma unroll
    for (int off = 1; off < 1024; off <<= 1) {
        int v = (t >= off) ? s[t - off] : 0;
        __syncthreads();
        s[t] += v;
        __syncthreads();
    }
    if (i < NN) g_rp[i] = s[t] - x;           // block-local exclusive
    if (t == 1023) g_bsum[blockIdx.x] = s[1023];
}
__global__ void scan2_kernel(int nblk) {      // 1 block x 128, parallel scan
    __shared__ int s[128];
    int t = threadIdx.x;
    int v = (t < nblk) ? g_bsum[t] : 0;
    s[t] = v;
    __syncthreads();
    #pragma unroll
    for (int off = 1; off < 128; off <<= 1) {
        int u = (t >= off) ? s[t - off] : 0;
        __syncthreads();
        s[t] += u;
        __syncthreads();
    }
    if (t < nblk) g_boff[t] = s[t] - v;       // exclusive
}
__global__ void fin_kernel() {
    int i = blockIdx.x * blockDim.x + threadIdx.x;
    if (i >= NN) return;
    int rp = g_rp[i] + g_boff[i >> 10];
    g_rp[i] = rp;
    g_cur[i] = rp;
    g_deg[i] = rsqrtf(1.0f + (float)g_cnt[i]);
    if (i == 0) g_rp[NN] = NE;
}
__global__ void scatter_kernel(const int* __restrict__ ei) {
    int e = blockIdx.x * blockDim.x + threadIdx.x;
    if (e >= NE) return;
    int c = ei[NE + e];
    int slot = atomicAdd(&g_cur[c], 1);
    g_csr[slot] = ei[e];
}

// ------- aggregation + residual combine + fp16 split, warp per node --------
__global__ void agg_kernel(const float* __restrict__ src) {
    int gid  = blockIdx.x * blockDim.x + threadIdx.x;
    int node = gid >> 5;
    if (node >= NN) return;
    int lane = gid & 31;
    const float4* s4 = (const float4*)src;
    float dn = g_deg[node];
    float4 acc = s4[(size_t)node * 32 + lane];
    float w0 = dn * dn;
    acc.x *= w0; acc.y *= w0; acc.z *= w0; acc.w *= w0;
    int j   = g_rp[node];
    int end = g_rp[node + 1];
    for (; j + 3 < end; j += 4) {
        int s0 = g_csr[j],     s1 = g_csr[j + 1];
        int s2 = g_csr[j + 2], s3 = g_csr[j + 3];
        float q0 = dn * g_deg[s0], q1 = dn * g_deg[s1];
        float q2 = dn * g_deg[s2], q3 = dn * g_deg[s3];
        float4 v0 = s4[(size_t)s0 * 32 + lane];
        float4 v1 = s4[(size_t)s1 * 32 + lane];
        float4 v2 = s4[(size_t)s2 * 32 + lane];
        float4 v3 = s4[(size_t)s3 * 32 + lane];
        acc.x += q0 * v0.x + q1 * v1.x + q2 * v2.x + q3 * v3.x;
        acc.y += q0 * v0.y + q1 * v1.y + q2 * v2.y + q3 * v3.y;
        acc.z += q0 * v0.z + q1 * v1.z + q2 * v2.z + q3 * v3.z;
        acc.w += q0 * v0.w + q1 * v1.w + q2 * v2.w + q3 * v3.w;
    }
    for (; j < end; j++) {
        int sa = g_csr[j];
        float wa = dn * g_deg[sa];
        float4 va = s4[(size_t)sa * 32 + lane];
        acc.x += wa * va.x; acc.y += wa * va.y;
        acc.z += wa * va.z; acc.w += wa * va.w;
    }
    float4 h0v = ((const float4*)g_h0)[(size_t)node * 32 + lane];
    float cx = 0.9f * acc.x + 0.1f * h0v.x;
    float cy = 0.9f * acc.y + 0.1f * h0v.y;
    float cz = 0.9f * acc.z + 0.1f * h0v.z;
    float cw = 0.9f * acc.w + 0.1f * h0v.w;
    __half hx, lx, hy, ly, hz, lz, hw, lw;
    split_f16(cx, hx, lx); split_f16(cy, hy, ly);
    split_f16(cz, hz, lz); split_f16(cw, hw, lw);
    half2* ph = (half2*)(g_comb_hi + (size_t)node * HD) + lane * 2;
    half2* pl = (half2*)(g_comb_lo + (size_t)node * HD) + lane * 2;
    ph[0] = __halves2half2(hx, hy); ph[1] = __halves2half2(hz, hw);
    pl[0] = __halves2half2(lx, ly); pl[1] = __halves2half2(lz, lw);
}

// ---------------- weight transpose + fp16 split ----------------
__global__ void prep_weights(const float* __restrict__ w1,
                             const float* __restrict__ cw,
                             const float* __restrict__ w2) {
    int i = blockIdx.x * blockDim.x + threadIdx.x;
    const int N1 = HD * DIN;
    const int N2 = 2 * HD * HD;
    const int N3 = DOUT * HD;
    if (i < N1) {
        int n = i / DIN, k = i % DIN;
        split_f16(w1[(size_t)k * HD + n], g_w1t_hi[i], g_w1t_lo[i]);
    } else if (i < N1 + N2) {
        int j = i - N1;
        int l = j / (HD * HD), r = j % (HD * HD);
        int n = r / HD, k = r % HD;
        split_f16(cw[(size_t)l * HD * HD + (size_t)k * HD + n], g_cwt_hi[j], g_cwt_lo[j]);
    } else if (i < N1 + N2 + N3) {
        int j = i - N1 - N2;
        int n = j / HD, k = j % HD;
        split_f16(w2[(size_t)k * DOUT + n], g_w2t_hi[j], g_w2t_lo[j]);
    }
}

// ======== templated GEMM compute core ========
// MF m-frags (16 rows each), NF n-frags (8 cols), NKS k16-steps per tile.
// ABB/BBB: bytes per A/B buffer (per component). BKPB: row stride in bytes.
template<int MF, int NF, int NKS, int ABB, int BBB, int BKPB>
__device__ __forceinline__ void gemm_compute(
    uint32_t uAH, uint32_t uAL, uint32_t uBH, uint32_t uBL,
    int b, int wm, int wn, int a_r, int a_kc, int b_r, int b_kc,
    float (*acc)[NF][4])
{
    #pragma unroll
    for (int ks = 0; ks < NKS; ks++) {
        uint32_t ah[MF][4], al[MF][4];
        #pragma unroll
        for (int mf = 0; mf < MF; mf++) {
            uint32_t off = (uint32_t)(wm + mf * 16 + a_r) * BKPB + ks * 32 + a_kc * 16;
            ldsm4(ah[mf], uAH + (uint32_t)b * ABB + off);
            ldsm4(al[mf], uAL + (uint32_t)b * ABB + off);
        }
        uint32_t bh[NF][2], bl[NF][2];
        #pragma unroll
        for (int nb = 0; nb < NF / 2; nb++) {
            uint32_t off = (uint32_t)(wn + nb * 16 + b_r) * BKPB + ks * 32 + b_kc * 16;
            uint32_t t[4];
            ldsm4(t, uBH + (uint32_t)b * BBB + off);
            bh[2 * nb][0] = t[0]; bh[2 * nb][1] = t[1];
            bh[2 * nb + 1][0] = t[2]; bh[2 * nb + 1][1] = t[3];
            ldsm4(t, uBL + (uint32_t)b * BBB + off);
            bl[2 * nb][0] = t[0]; bl[2 * nb][1] = t[1];
            bl[2 * nb + 1][0] = t[2]; bl[2 * nb + 1][1] = t[3];
        }
        #pragma unroll
        for (int mf = 0; mf < MF; mf++)
            #pragma unroll
            for (int nf = 0; nf < NF; nf++) {
                mma_f16(acc[mf][nf], ah[mf], bh[nf]);
                mma_f16(acc[mf][nf], ah[mf], bl[nf]);
                mma_f16(acc[mf][nf], al[mf], bh[nf]);
            }
    }
}

template<int MF, int BN, int NF, bool RELU, bool BIAS>
__device__ __forceinline__ void gemm_epilogue(
    float (*acc)[NF][4], const float* bias, float* C,
    int M, int blockM, int wm, int wn, int lane)
{
    #pragma unroll
    for (int mf = 0; mf < MF; mf++) {
        int row0 = blockM + wm + mf * 16 + (lane >> 2);
        #pragma unroll
        for (int nf = 0; nf < NF; nf++) {
            int col = wn + nf * 8 + (lane & 3) * 2;
            float2 v0 = make_float2(acc[mf][nf][0], acc[mf][nf][1]);
            float2 v1 = make_float2(acc[mf][nf][2], acc[mf][nf][3]);
            if (BIAS) {
                float b0 = bias[col], b1 = bias[col + 1];
                v0.x += b0; v0.y += b1;
                v1.x += b0; v1.y += b1;
            }
            if (RELU) {
                v0.x = fmaxf(v0.x, 0.f); v0.y = fmaxf(v0.y, 0.f);
                v1.x = fmaxf(v1.x, 0.f); v1.y = fmaxf(v1.y, 0.f);
            }
            if (row0 < M)     *(float2*)(C + (size_t)row0 * BN + col)       = v0;
            if (row0 + 8 < M) *(float2*)(C + (size_t)(row0 + 8) * BN + col) = v1;
        }
    }
}

// ===== GEMM1: fp32 A, BK=64, 512 threads, 1 CTA/SM, warp tile 32x32 =====
// BKP = 72 halves (144 B row stride). K must be a multiple of 64.
#define K64_BKP   72
#define K64_ABB   (128 * K64_BKP * 2)     // 18432 B per buf per comp
template<int BN, bool RELU, bool BIAS>
__global__ void __launch_bounds__(512, 1)
mma_gemm_f32_k64(const float* __restrict__ A,
                 const __half* __restrict__ Bhi, const __half* __restrict__ Blo,
                 const float* __restrict__ bias, float* __restrict__ C,
                 int M, int K)
{
    constexpr int BM = 128, BK = 64;
    constexpr int MF = 2;
    constexpr int WN = BN / 4;                      // 32
    constexpr int NF = WN / 8;                      // 4
    constexpr int ASZ = BM * K64_BKP;               // halves per comp per buf
    constexpr int BBB = BN * K64_BKP * 2;           // B buf bytes per comp

    extern __shared__ __half smh[];
    __half* AHp = smh;                 // [2][ASZ]
    __half* ALp = smh + 2 * ASZ;
    const uint32_t sb  = smem_to_u32(smh);
    const uint32_t uAH = sb;
    const uint32_t uAL = sb + 2 * K64_ABB;
    const uint32_t uBH = sb + 4 * K64_ABB;
    const uint32_t uBL = sb + 4 * K64_ABB + 2 * BBB;

    const int tid  = threadIdx.x;
    const int lane = tid & 31;
    const int wid  = tid >> 5;                      // 0..15
    const int wm   = (wid >> 2) * 32;               // 4 row-groups of 32
    const int wn   = (wid & 3) * WN;
    const int blockM = blockIdx.x * BM;

    const int a_r  = lane & 15, a_kc = lane >> 4;
    const int b_r  = (lane & 7) + ((lane >> 4) << 3);
    const int b_kc = (lane >> 3) & 1;

    float acc[MF][NF][4];
    #pragma unroll
    for (int mf = 0; mf < MF; mf++)
        #pragma unroll
        for (int nf = 0; nf < NF; nf++)
            #pragma unroll
            for (int q = 0; q < 4; q++) acc[mf][nf][q] = 0.0f;

    const int nit = K / BK;

    auto fillB = [&](int i, int b) {
        constexpr int CH = BN * 8;                  // 16B chunks per comp (1024)
        #pragma unroll
        for (int it = 0; it < CH / 512; it++) {
            int id = tid + it * 512;
            int n = id >> 3, c = id & 7;
            uint32_t off = (uint32_t)b * BBB + (uint32_t)n * (K64_BKP * 2) + c * 16;
            cp_async16(uBH + off, Bhi + (size_t)n * K + i * BK + c * 8);
            cp_async16(uBL + off, Blo + (size_t)n * K + i * BK + c * 8);
        }
    };
    float4 aR[4];
    auto loadA = [&](int i) {
        #pragma unroll
        for (int it = 0; it < 4; it++) {
            int id  = tid + it * 512;               // BM*16 f4-chunks = 2048
            int row = id >> 4, c4 = id & 15;
            int gr  = blockM + row;
            float4 v = make_float4(0.f, 0.f, 0.f, 0.f);
            if (gr < M)
                v = *(const float4*)(A + (size_t)gr * K + i * BK + c4 * 4);
            aR[it] = v;
        }
    };
    auto storeA = [&](int b) {
        #pragma unroll
        for (int it = 0; it < 4; it++) {
            int id  = tid + it * 512;
            int row = id >> 4, c4 = id & 15;
            float4 v = aR[it];
            __half hx, lx, hy, ly, hz, lz, hw, lw;
            split_f16(v.x, hx, lx); split_f16(v.y, hy, ly);
            split_f16(v.z, hz, lz); split_f16(v.w, hw, lw);
            int off = b * ASZ + row * K64_BKP + c4 * 4;
            ((half2*)(AHp + off))[0] = __halves2half2(hx, hy);
            ((half2*)(AHp + off))[1] = __halves2half2(hz, hw);
            ((half2*)(ALp + off))[0] = __halves2half2(lx, ly);
            ((half2*)(ALp + off))[1] = __halves2half2(lz, lw);
        }
    };

    // prologue
    loadA(0);
    storeA(0);
    fillB(0, 0);
    cp_commit();

    // race-free mainloop
    for (int i = 0; i < nit; i++) {
        const int b = i & 1;
        cp_wait<0>();
        __syncthreads();
        if (i + 1 < nit) {
            fillB(i + 1, b ^ 1);
            cp_commit();
            loadA(i + 1);
        }
        gemm_compute<MF, NF, 4, K64_ABB, BBB, K64_BKP * 2>(
            uAH, uAL, uBH, uBL, b, wm, wn, a_r, a_kc, b_r, b_kc, acc);
        if (i + 1 < nit) storeA(b ^ 1);
    }

    gemm_epilogue<MF, BN, NF, RELU, BIAS>(acc, bias, C, M, blockM, wm, wn, lane);
}

// ======= BK=32 variants (256 threads, 2 CTAs/SM), proven geometry =======
#define BKP 40
#define AB_BYTES (128 * BKP * 2)

// fp32 A (split on the fly): used for logits GEMM
template<int BN, bool RELU, bool BIAS>
__global__ void __launch_bounds__(256, 2)
mma_gemm_f32(const float* __restrict__ A,
             const __half* __restrict__ Bhi, const __half* __restrict__ Blo,
             const float* __restrict__ bias, float* __restrict__ C,
             int M, int K)
{
    constexpr int BM = 128, BK = 32;
    constexpr int MF = 4;
    constexpr int WN = BN / 4;
    constexpr int NF = WN / 8;
    constexpr int ASZ = BM * BKP;
    constexpr int BBB = BN * BKP * 2;

    extern __shared__ __half smh[];
    __half* AHp = smh;
    __half* ALp = smh + 2 * ASZ;
    const uint32_t sb  = smem_to_u32(smh);
    const uint32_t uAH = sb;
    const uint32_t uAL = sb + 2 * AB_BYTES;
    const uint32_t uBH = sb + 4 * AB_BYTES;
    const uint32_t uBL = sb + 4 * AB_BYTES + 2 * BBB;

    const int tid  = threadIdx.x;
    const int lane = tid & 31;
    const int wid  = tid >> 5;
    const int wm   = (wid >> 2) * 64;
    const int wn   = (wid & 3) * WN;
    const int blockM = blockIdx.x * BM;

    const int a_r  = lane & 15, a_kc = lane >> 4;
    const int b_r  = (lane & 7) + ((lane >> 4) << 3);
    const int b_kc = (lane >> 3) & 1;

    float acc[MF][NF][4];
    #pragma unroll
    for (int mf = 0; mf < MF; mf++)
        #pragma unroll
        for (int nf = 0; nf < NF; nf++)
            #pragma unroll
            for (int q = 0; q < 4; q++) acc[mf][nf][q] = 0.0f;

    const int nit = K / BK;

    auto fillB = [&](int i, int b) {
        constexpr int CH = BN * 4;
        #pragma unroll
        for (int it = 0; it < (CH + 255) / 256; it++) {
            int id = tid + it * 256;
            if (CH % 256 == 0 || id < CH) {
                int n = id >> 2, c = id & 3;
                uint32_t off = (uint32_t)b * BBB + (uint32_t)n * (BKP * 2) + c * 16;
                cp_async16(uBH + off, Bhi + (size_t)n * K + i * BK + c * 8);
                cp_async16(uBL + off, Blo + (size_t)n * K + i * BK + c * 8);
            }
        }
    };
    float4 aR[4];
    auto loadA = [&](int i) {
        #pragma unroll
        for (int it = 0; it < 4; it++) {
            int id  = tid + it * 256;
            int row = id >> 3, c4 = id & 7;
            int gr  = blockM + row;
            float4 v = make_float4(0.f, 0.f, 0.f, 0.f);
            if (gr < M)
                v = *(const float4*)(A + (size_t)gr * K + i * BK + c4 * 4);
            aR[it] = v;
        }
    };
    auto storeA = [&](int b) {
        #pragma unroll
        for (int it = 0; it < 4; it++) {
            int id  = tid + it * 256;
            int row = id >> 3, c4 = id & 7;
            float4 v = aR[it];
            __half hx, lx, hy, ly, hz, lz, hw, lw;
            split_f16(v.x, hx, lx); split_f16(v.y, hy, ly);
            split_f16(v.z, hz, lz); split_f16(v.w, hw, lw);
            int off = b * ASZ + row * BKP + c4 * 4;
            ((half2*)(AHp + off))[0] = __halves2half2(hx, hy);
            ((half2*)(AHp + off))[1] = __halves2half2(hz, hw);
            ((half2*)(ALp + off))[0] = __halves2half2(lx, ly);
            ((half2*)(ALp + off))[1] = __halves2half2(lz, lw);
        }
    };

    loadA(0);
    storeA(0);
    fillB(0, 0);
    cp_commit();

    for (int i = 0; i < nit; i++) {
        const int b = i & 1;
        cp_wait<0>();
        __syncthreads();
        if (i + 1 < nit) {
            fillB(i + 1, b ^ 1);
            cp_commit();
            loadA(i + 1);
        }
        gemm_compute<MF, NF, 2, AB_BYTES, BBB, BKP * 2>(
            uAH, uAL, uBH, uBL, b, wm, wn, a_r, a_kc, b_r, b_kc, acc);
        if (i + 1 < nit) storeA(b ^ 1);
    }

    gemm_epilogue<MF, BN, NF, RELU, BIAS>(acc, bias, C, M, blockM, wm, wn, lane);
}

// pre-split fp16 A (pure cp.async): conv GEMMs
template<int BN>
__global__ void __launch_bounds__(256, 2)
mma_gemm_f16(const __half* __restrict__ Ahi, const __half* __restrict__ Alo,
             const __half* __restrict__ Bhi, const __half* __restrict__ Blo,
             float* __restrict__ C, int M, int K)
{
    constexpr int BM = 128, BK = 32;
    constexpr int MF = 4;
    constexpr int WN = BN / 4;
    constexpr int NF = WN / 8;
    constexpr int BBB = BN * BKP * 2;

    extern __shared__ __half smh[];
    const uint32_t sb  = smem_to_u32(smh);
    const uint32_t uAH = sb;
    const uint32_t uAL = sb + 2 * AB_BYTES;
    const uint32_t uBH = sb + 4 * AB_BYTES;
    const uint32_t uBL = sb + 4 * AB_BYTES + 2 * BBB;

    const int tid  = threadIdx.x;
    const int lane = tid & 31;
    const int wid  = tid >> 5;
    const int wm   = (wid >> 2) * 64;
    const int wn   = (wid & 3) * WN;
    const int blockM = blockIdx.x * BM;

    const int a_r  = lane & 15, a_kc = lane >> 4;
    const int b_r  = (lane & 7) + ((lane >> 4) << 3);
    const int b_kc = (lane >> 3) & 1;

    float acc[MF][NF][4];
    #pragma unroll
    for (int mf = 0; mf < MF; mf++)
        #pragma unroll
        for (int nf = 0; nf < NF; nf++)
            #pragma unroll
            for (int q = 0; q < 4; q++) acc[mf][nf][q] = 0.0f;

    const int nit = K / BK;

    auto fillA = [&](int i, int b) {
        constexpr int CH = BM * 4;
        #pragma unroll
        for (int it = 0; it < CH / 256; it++) {
            int id = tid + it * 256;
            int row = id >> 2, c = id & 3;
            int gr = blockM + row;
            if (gr < M) {
                uint32_t off = (uint32_t)b * AB_BYTES + (uint32_t)row * (BKP * 2) + c * 16;
                cp_async16(uAH + off, Ahi + (size_t)gr * K + i * BK + c * 8);
                cp_async16(uAL + off, Alo + (size_t)gr * K + i * BK + c * 8);
            }
        }
    };
    auto fillB = [&](int i, int b) {
        constexpr int CH = BN * 4;
        #pragma unroll
        for (int it = 0; it < (CH + 255) / 256; it++) {
            int id = tid + it * 256;
            if (CH % 256 == 0 || id < CH) {
                int n = id >> 2, c = id & 3;
                uint32_t off = (uint32_t)b * BBB + (uint32_t)n * (BKP * 2) + c * 16;
                cp_async16(uBH + off, Bhi + (size_t)n * K + i * BK + c * 8);
                cp_async16(uBL + off, Blo + (size_t)n * K + i * BK + c * 8);
            }
        }
    };

    fillA(0, 0);
    fillB(0, 0);
    cp_commit();

    for (int i = 0; i < nit; i++) {
        const int b = i & 1;
        cp_wait<0>();
        __syncthreads();
        if (i + 1 < nit) {
            fillA(i + 1, b ^ 1);
            fillB(i + 1, b ^ 1);
            cp_commit();
        }
        gemm_compute<MF, NF, 2, AB_BYTES, BBB, BKP * 2>(
            uAH, uAL, uBH, uBL, b, wm, wn, a_r, a_kc, b_r, b_kc, acc);
    }

    gemm_epilogue<MF, BN, NF, false, false>(acc, nullptr, C, M, blockM, wm, wn, lane);
}

// ---------------- launch ----------------
extern "C" void kernel_launch(void* const* d_in, const int* in_sizes, int n_in,
                              void* d_out, int out_size)
{
    const float* x  = (const float*)d_in[0];
    const int*   ei = (const int*)  d_in[1];
    const float* w1 = (const float*)d_in[2];
    const float* b1 = (const float*)d_in[3];
    const float* cw = (const float*)d_in[4];
    const float* w2 = (const float*)d_in[5];
    const float* b2 = (const float*)d_in[6];

    float* out    = (float*)d_out;
    float* hout   = out;
    float* logits = out + (size_t)NN * HD;

    float *p_h0, *p_h;
    __half *p_chi, *p_clo;
    __half *p_w1h, *p_w1l, *p_cwh, *p_cwl, *p_w2h, *p_w2l;
    cudaGetSymbolAddress((void**)&p_h0,  g_h0);
    cudaGetSymbolAddress((void**)&p_h,   g_h);
    cudaGetSymbolAddress((void**)&p_chi, g_comb_hi);
    cudaGetSymbolAddress((void**)&p_clo, g_comb_lo);
    cudaGetSymbolAddress((void**)&p_w1h, g_w1t_hi);
    cudaGetSymbolAddress((void**)&p_w1l, g_w1t_lo);
    cudaGetSymbolAddress((void**)&p_cwh, g_cwt_hi);
    cudaGetSymbolAddress((void**)&p_cwl, g_cwt_lo);
    cudaGetSymbolAddress((void**)&p_w2h, g_w2t_hi);
    cudaGetSymbolAddress((void**)&p_w2l, g_w2t_lo);

    const int TPB = 256;
    const int gemm_grid = (NN + 127) / 128;                    // 782
    const int NBLK = (NN + 1023) / 1024;                       // 98
    const int SMEM_K64 = 4 * K64_ABB + 4 * 128 * K64_BKP * 2;  // 147456 B
    const int SMEM_128 = 4 * AB_BYTES + 4 * 128 * BKP * 2;     // 81920 B
    const int SMEM_64  = 4 * AB_BYTES + 4 * 64 * BKP * 2;      // 61440 B

    cudaFuncSetAttribute(mma_gemm_f32_k64<128, true, true>,
                         cudaFuncAttributeMaxDynamicSharedMemorySize, SMEM_K64);
    cudaFuncSetAttribute(mma_gemm_f16<128>,
                         cudaFuncAttributeMaxDynamicSharedMemorySize, SMEM_128);
    cudaFuncSetAttribute(mma_gemm_f32<64, false, true>,
                         cudaFuncAttributeMaxDynamicSharedMemorySize, SMEM_64);

    // launches 1-3, then gemm1 as launch #4 (profiler capture slot)
    cnt_init_kernel <<<(NN + TPB - 1) / TPB, TPB>>>();
    cnt_accum_kernel<<<(NE + TPB - 1) / TPB, TPB>>>(ei);
    prep_weights    <<<(HD*DIN + 2*HD*HD + DOUT*HD + TPB - 1) / TPB, TPB>>>(w1, cw, w2);

    // h0 = relu(x @ w1 + b1)   [launch #4 -> profiled]  BK=64, 512 threads
    mma_gemm_f32_k64<128, true, true><<<gemm_grid, 512, SMEM_K64>>>(
        x, p_w1h, p_w1l, b1, p_h0, NN, DIN);

    // rest of CSR build
    scan1_kernel    <<<NBLK, 1024>>>();
    scan2_kernel    <<<1, 128>>>(NBLK);
    fin_kernel      <<<(NN + TPB - 1) / TPB, TPB>>>();
    scatter_kernel  <<<(NE + TPB - 1) / TPB, TPB>>>(ei);

    // ---- layer 1: agg(h0) + combine + split -> comb; h = comb @ cw0 ----
    agg_kernel<<<(NN * 32 + TPB - 1) / TPB, TPB>>>(p_h0);
    mma_gemm_f16<128><<<gemm_grid, 256, SMEM_128>>>(
        p_chi, p_clo, p_cwh, p_cwl, p_h, NN, HD);

    // ---- layer 2: agg(h) + combine + split -> comb; hout = comb @ cw1 ----
    agg_kernel<<<(NN * 32 + TPB - 1) / TPB, TPB>>>(p_h);
    mma_gemm_f16<128><<<gemm_grid, 256, SMEM_128>>>(
        p_chi, p_clo, p_cwh + HD * HD, p_cwl + HD * HD, hout, NN, HD);

    // logits = hout @ w2 + b2
    mma_gemm_f32<64, false, true><<<gemm_grid, 256, SMEM_64>>>(
        hout, p_w2h, p_w2l, b2, logits, NN, HD);
}

// round 13
// speedup vs baseline: 1.1319x; 1.1319x over previous
#include <cuda_runtime.h>
#include <cuda_fp16.h>
#include <cstdint>

#define NN   100000
#define NE   1600000
#define DIN  512
#define HD   128
#define DOUT 64

// ---------------- scratch (device globals: allocation-free) ----------------
__device__ float g_deg[NN];                     // dinv
__device__ float g_h0 [(size_t)NN * HD];
__device__ float g_h  [(size_t)NN * HD];
__device__ __half g_comb_hi[(size_t)NN * HD];
__device__ __half g_comb_lo[(size_t)NN * HD];
// CSR build
__device__ int g_cnt[NN];
__device__ int g_rp [NN + 1];
__device__ int g_cur[NN];
__device__ int g_csr[NE];
__device__ int g_bsum[128], g_boff[128];
// K-major, fp16-split weights: [N][K]
__device__ __half g_w1t_hi[HD * DIN],    g_w1t_lo[HD * DIN];
__device__ __half g_cwt_hi[2 * HD * HD], g_cwt_lo[2 * HD * HD];
__device__ __half g_w2t_hi[DOUT * HD],   g_w2t_lo[DOUT * HD];

// ======================= helpers =====================
__device__ __forceinline__ uint32_t smem_to_u32(const void* p) {
    uint32_t a;
    asm("{ .reg .u64 t; cvta.to.shared.u64 t, %1; cvt.u32.u64 %0, t; }" : "=r"(a) : "l"(p));
    return a;
}
__device__ __forceinline__ void ldsm4(uint32_t* r, uint32_t addr) {
    asm volatile("ldmatrix.sync.aligned.m8n8.x4.shared.b16 {%0,%1,%2,%3}, [%4];"
                 : "=r"(r[0]), "=r"(r[1]), "=r"(r[2]), "=r"(r[3]) : "r"(addr));
}
__device__ __forceinline__ void mma_f16(float* c, const uint32_t* a, const uint32_t* b) {
    asm volatile("mma.sync.aligned.m16n8k16.row.col.f32.f16.f16.f32 "
                 "{%0,%1,%2,%3}, {%4,%5,%6,%7}, {%8,%9}, {%0,%1,%2,%3};"
                 : "+f"(c[0]), "+f"(c[1]), "+f"(c[2]), "+f"(c[3])
                 : "r"(a[0]), "r"(a[1]), "r"(a[2]), "r"(a[3]), "r"(b[0]), "r"(b[1]));
}
__device__ __forceinline__ void cp_async16(uint32_t dst, const void* src) {
    asm volatile("cp.async.cg.shared.global [%0], [%1], 16;"
                 :: "r"(dst), "l"((unsigned long long)__cvta_generic_to_global(src)) : "memory");
}
__device__ __forceinline__ void cp_commit() {
    asm volatile("cp.async.commit_group;" ::: "memory");
}
template<int N> __device__ __forceinline__ void cp_wait() {
    asm volatile("cp.async.wait_group %0;" :: "n"(N) : "memory");
}
__device__ __forceinline__ void split_f16(float x, __half& hi, __half& lo) {
    hi = __float2half_rn(x);
    lo = __float2half_rn(x - __half2float(hi));
}

// ---------------- CSR build ----------------
__global__ void cnt_init_kernel() {
    int i = blockIdx.x * blockDim.x + threadIdx.x;
    if (i < NN) g_cnt[i] = 0;
}
__global__ void cnt_accum_kernel(const int* __restrict__ ei) {
    int e = blockIdx.x * blockDim.x + threadIdx.x;
    if (e < NE) atomicAdd(&g_cnt[ei[NE + e]], 1);
}
__global__ void scan1_kernel() {      // 98 blocks x 1024
    __shared__ int s[1024];
    int t = threadIdx.x;
    int i = blockIdx.x * 1024 + t;
    int x = (i < NN) ? g_cnt[i] : 0;
    s[t] = x;
    __syncthreads();
    #pragma unroll
    for (int off = 1; off < 1024; off <<= 1) {
        int v = (t >= off) ? s[t - off] : 0;
        __syncthreads();
        s[t] += v;
        __syncthreads();
    }
    if (i < NN) g_rp[i] = s[t] - x;
    if (t == 1023) g_bsum[blockIdx.x] = s[1023];
}
__global__ void scan2_kernel(int nblk) {
    __shared__ int s[128];
    int t = threadIdx.x;
    int v = (t < nblk) ? g_bsum[t] : 0;
    s[t] = v;
    __syncthreads();
    #pragma unroll
    for (int off = 1; off < 128; off <<= 1) {
        int u = (t >= off) ? s[t - off] : 0;
        __syncthreads();
        s[t] += u;
        __syncthreads();
    }
    if (t < nblk) g_boff[t] = s[t] - v;
}
__global__ void fin_kernel() {
    int i = blockIdx.x * blockDim.x + threadIdx.x;
    if (i >= NN) return;
    int rp = g_rp[i] + g_boff[i >> 10];
    g_rp[i] = rp;
    g_cur[i] = rp;
    g_deg[i] = rsqrtf(1.0f + (float)g_cnt[i]);
    if (i == 0) g_rp[NN] = NE;
}
__global__ void scatter_kernel(const int* __restrict__ ei) {
    int e = blockIdx.x * blockDim.x + threadIdx.x;
    if (e >= NE) return;
    int c = ei[NE + e];
    int slot = atomicAdd(&g_cur[c], 1);
    g_csr[slot] = ei[e];
}

// ------- aggregation + residual combine + fp16 split, warp per node, MLP=8 -
__global__ void agg_kernel(const float* __restrict__ src) {
    int gid  = blockIdx.x * blockDim.x + threadIdx.x;
    int node = gid >> 5;
    if (node >= NN) return;
    int lane = gid & 31;
    const float4* s4 = (const float4*)src;
    float dn = g_deg[node];
    float4 acc = s4[(size_t)node * 32 + lane];
    float w0 = dn * dn;
    acc.x *= w0; acc.y *= w0; acc.z *= w0; acc.w *= w0;
    int j   = g_rp[node];
    int end = g_rp[node + 1];
    for (; j + 7 < end; j += 8) {
        int   si[8];
        float qi[8];
        float4 vi[8];
        #pragma unroll
        for (int u = 0; u < 8; u++) si[u] = g_csr[j + u];
        #pragma unroll
        for (int u = 0; u < 8; u++) qi[u] = dn * g_deg[si[u]];
        #pragma unroll
        for (int u = 0; u < 8; u++) vi[u] = s4[(size_t)si[u] * 32 + lane];
        #pragma unroll
        for (int u = 0; u < 8; u++) {
            acc.x += qi[u] * vi[u].x;
            acc.y += qi[u] * vi[u].y;
            acc.z += qi[u] * vi[u].z;
            acc.w += qi[u] * vi[u].w;
        }
    }
    for (; j + 3 < end; j += 4) {
        int s0 = g_csr[j],     s1 = g_csr[j + 1];
        int s2 = g_csr[j + 2], s3 = g_csr[j + 3];
        float q0 = dn * g_deg[s0], q1 = dn * g_deg[s1];
        float q2 = dn * g_deg[s2], q3 = dn * g_deg[s3];
        float4 v0 = s4[(size_t)s0 * 32 + lane];
        float4 v1 = s4[(size_t)s1 * 32 + lane];
        float4 v2 = s4[(size_t)s2 * 32 + lane];
        float4 v3 = s4[(size_t)s3 * 32 + lane];
        acc.x += q0 * v0.x + q1 * v1.x + q2 * v2.x + q3 * v3.x;
        acc.y += q0 * v0.y + q1 * v1.y + q2 * v2.y + q3 * v3.y;
        acc.z += q0 * v0.z + q1 * v1.z + q2 * v2.z + q3 * v3.z;
        acc.w += q0 * v0.w + q1 * v1.w + q2 * v2.w + q3 * v3.w;
    }
    for (; j < end; j++) {
        int sa = g_csr[j];
        float wa = dn * g_deg[sa];
        float4 va = s4[(size_t)sa * 32 + lane];
        acc.x += wa * va.x; acc.y += wa * va.y;
        acc.z += wa * va.z; acc.w += wa * va.w;
    }
    float4 h0v = ((const float4*)g_h0)[(size_t)node * 32 + lane];
    float cx = 0.9f * acc.x + 0.1f * h0v.x;
    float cy = 0.9f * acc.y + 0.1f * h0v.y;
    float cz = 0.9f * acc.z + 0.1f * h0v.z;
    float cw = 0.9f * acc.w + 0.1f * h0v.w;
    __half hx, lx, hy, ly, hz, lz, hw, lw;
    split_f16(cx, hx, lx); split_f16(cy, hy, ly);
    split_f16(cz, hz, lz); split_f16(cw, hw, lw);
    half2* ph = (half2*)(g_comb_hi + (size_t)node * HD) + lane * 2;
    half2* pl = (half2*)(g_comb_lo + (size_t)node * HD) + lane * 2;
    ph[0] = __halves2half2(hx, hy); ph[1] = __halves2half2(hz, hw);
    pl[0] = __halves2half2(lx, ly); pl[1] = __halves2half2(lz, lw);
}

// ---------------- weight transpose + fp16 split ----------------
__global__ void prep_weights(const float* __restrict__ w1,
                             const float* __restrict__ cw,
                             const float* __restrict__ w2) {
    int i = blockIdx.x * blockDim.x + threadIdx.x;
    const int N1 = HD * DIN;
    const int N2 = 2 * HD * HD;
    const int N3 = DOUT * HD;
    if (i < N1) {
        int n = i / DIN, k = i % DIN;
        split_f16(w1[(size_t)k * HD + n], g_w1t_hi[i], g_w1t_lo[i]);
    } else if (i < N1 + N2) {
        int j = i - N1;
        int l = j / (HD * HD), r = j % (HD * HD);
        int n = r / HD, k = r % HD;
        split_f16(cw[(size_t)l * HD * HD + (size_t)k * HD + n], g_cwt_hi[j], g_cwt_lo[j]);
    } else if (i < N1 + N2 + N3) {
        int j = i - N1 - N2;
        int n = j / HD, k = j % HD;
        split_f16(w2[(size_t)k * DOUT + n], g_w2t_hi[j], g_w2t_lo[j]);
    }
}

// ======== shared GEMM pieces (BM=128, BK=32, 8 warps, 2 CTAs/SM) ========
#define BKP 40
#define AB_BYTES (128 * BKP * 2)

// 3-term compute (convs/logits)
template<int MF, int NF, int NKS, int ABB, int BBB, int BKPB>
__device__ __forceinline__ void gemm_compute(
    uint32_t uAH, uint32_t uAL, uint32_t uBH, uint32_t uBL,
    int b, int wm, int wn, int a_r, int a_kc, int b_r, int b_kc,
    float (*acc)[NF][4])
{
    #pragma unroll
    for (int ks = 0; ks < NKS; ks++) {
        uint32_t ah[MF][4], al[MF][4];
        #pragma unroll
        for (int mf = 0; mf < MF; mf++) {
            uint32_t off = (uint32_t)(wm + mf * 16 + a_r) * BKPB + ks * 32 + a_kc * 16;
            ldsm4(ah[mf], uAH + (uint32_t)b * ABB + off);
            ldsm4(al[mf], uAL + (uint32_t)b * ABB + off);
        }
        uint32_t bh[NF][2], bl[NF][2];
        #pragma unroll
        for (int nb = 0; nb < NF / 2; nb++) {
            uint32_t off = (uint32_t)(wn + nb * 16 + b_r) * BKPB + ks * 32 + b_kc * 16;
            uint32_t t[4];
            ldsm4(t, uBH + (uint32_t)b * BBB + off);
            bh[2 * nb][0] = t[0]; bh[2 * nb][1] = t[1];
            bh[2 * nb + 1][0] = t[2]; bh[2 * nb + 1][1] = t[3];
            ldsm4(t, uBL + (uint32_t)b * BBB + off);
            bl[2 * nb][0] = t[0]; bl[2 * nb][1] = t[1];
            bl[2 * nb + 1][0] = t[2]; bl[2 * nb + 1][1] = t[3];
        }
        #pragma unroll
        for (int mf = 0; mf < MF; mf++)
            #pragma unroll
            for (int nf = 0; nf < NF; nf++) {
                mma_f16(acc[mf][nf], ah[mf], bh[nf]);
                mma_f16(acc[mf][nf], ah[mf], bl[nf]);
                mma_f16(acc[mf][nf], al[mf], bh[nf]);
            }
    }
}

template<int MF, int BN, int NF, bool RELU, bool BIAS>
__device__ __forceinline__ void gemm_epilogue(
    float (*acc)[NF][4], const float* bias, float* C,
    int M, int blockM, int wm, int wn, int lane)
{
    #pragma unroll
    for (int mf = 0; mf < MF; mf++) {
        int row0 = blockM + wm + mf * 16 + (lane >> 2);
        #pragma unroll
        for (int nf = 0; nf < NF; nf++) {
            int col = wn + nf * 8 + (lane & 3) * 2;
            float2 v0 = make_float2(acc[mf][nf][0], acc[mf][nf][1]);
            float2 v1 = make_float2(acc[mf][nf][2], acc[mf][nf][3]);
            if (BIAS) {
                float b0 = bias[col], b1 = bias[col + 1];
                v0.x += b0; v0.y += b1;
                v1.x += b0; v1.y += b1;
            }
            if (RELU) {
                v0.x = fmaxf(v0.x, 0.f); v0.y = fmaxf(v0.y, 0.f);
                v1.x = fmaxf(v1.x, 0.f); v1.y = fmaxf(v1.y, 0.f);
            }
            if (row0 < M)     *(float2*)(C + (size_t)row0 * BN + col)       = v0;
            if (row0 + 8 < M) *(float2*)(C + (size_t)(row0 + 8) * BN + col) = v1;
        }
    }
}

// ===== GEMM1: 2-term (A exact via hi+lo, B rounded to fp16 hi only) =====
// C = A @ Bh^T : MMA count 2/3 of the 3-term kernel; B-lo never touched.
template<int BN, bool RELU, bool BIAS>
__global__ void __launch_bounds__(256, 2)
mma_gemm_f32_2t(const float* __restrict__ A,
                const __half* __restrict__ Bhi,
                const float* __restrict__ bias, float* __restrict__ C,
                int M, int K)
{
    constexpr int BM = 128, BK = 32;
    constexpr int MF = 4;
    constexpr int WN = BN / 4;
    constexpr int NF = WN / 8;
    constexpr int ASZ = BM * BKP;
    constexpr int BBB = BN * BKP * 2;

    extern __shared__ __half smh[];
    __half* AHp = smh;
    __half* ALp = smh + 2 * ASZ;
    const uint32_t sb  = smem_to_u32(smh);
    const uint32_t uAH = sb;
    const uint32_t uAL = sb + 2 * AB_BYTES;
    const uint32_t uBH = sb + 4 * AB_BYTES;

    const int tid  = threadIdx.x;
    const int lane = tid & 31;
    const int wid  = tid >> 5;
    const int wm   = (wid >> 2) * 64;
    const int wn   = (wid & 3) * WN;
    const int blockM = blockIdx.x * BM;

    const int a_r  = lane & 15, a_kc = lane >> 4;
    const int b_r  = (lane & 7) + ((lane >> 4) << 3);
    const int b_kc = (lane >> 3) & 1;

    float acc[MF][NF][4];
    #pragma unroll
    for (int mf = 0; mf < MF; mf++)
        #pragma unroll
        for (int nf = 0; nf < NF; nf++)
            #pragma unroll
            for (int q = 0; q < 4; q++) acc[mf][nf][q] = 0.0f;

    const int nit = K / BK;

    auto fillB = [&](int i, int b) {
        constexpr int CH = BN * 4;
        #pragma unroll
        for (int it = 0; it < (CH + 255) / 256; it++) {
            int id = tid + it * 256;
            if (CH % 256 == 0 || id < CH) {
                int n = id >> 2, c = id & 3;
                uint32_t off = (uint32_t)b * BBB + (uint32_t)n * (BKP * 2) + c * 16;
                cp_async16(uBH + off, Bhi + (size_t)n * K + i * BK + c * 8);
            }
        }
    };
    float4 aR[4];
    auto loadA = [&](int i) {
        #pragma unroll
        for (int it = 0; it < 4; it++) {
            int id  = tid + it * 256;
            int row = id >> 3, c4 = id & 7;
            int gr  = blockM + row;
            float4 v = make_float4(0.f, 0.f, 0.f, 0.f);
            if (gr < M)
                v = *(const float4*)(A + (size_t)gr * K + i * BK + c4 * 4);
            aR[it] = v;
        }
    };
    auto storeA = [&](int b) {
        #pragma unroll
        for (int it = 0; it < 4; it++) {
            int id  = tid + it * 256;
            int row = id >> 3, c4 = id & 7;
            float4 v = aR[it];
            __half hx, lx, hy, ly, hz, lz, hw, lw;
            split_f16(v.x, hx, lx); split_f16(v.y, hy, ly);
            split_f16(v.z, hz, lz); split_f16(v.w, hw, lw);
            int off = b * ASZ + row * BKP + c4 * 4;
            ((half2*)(AHp + off))[0] = __halves2half2(hx, hy);
            ((half2*)(AHp + off))[1] = __halves2half2(hz, hw);
            ((half2*)(ALp + off))[0] = __halves2half2(lx, ly);
            ((half2*)(ALp + off))[1] = __halves2half2(lz, lw);
        }
    };

    loadA(0);
    storeA(0);
    fillB(0, 0);
    cp_commit();

    for (int i = 0; i < nit; i++) {
        const int b = i & 1;
        cp_wait<0>();
        __syncthreads();
        if (i + 1 < nit) {
            fillB(i + 1, b ^ 1);
            cp_commit();
            loadA(i + 1);
        }
        // 2-term compute
        #pragma unroll
        for (int ks = 0; ks < 2; ks++) {
            uint32_t ah[MF][4], al[MF][4];
            #pragma unroll
            for (int mf = 0; mf < MF; mf++) {
                uint32_t off = (uint32_t)(wm + mf * 16 + a_r) * (BKP * 2) + ks * 32 + a_kc * 16;
                ldsm4(ah[mf], uAH + (uint32_t)b * AB_BYTES + off);
                ldsm4(al[mf], uAL + (uint32_t)b * AB_BYTES + off);
            }
            uint32_t bh[NF][2];
            #pragma unroll
            for (int nb = 0; nb < NF / 2; nb++) {
                uint32_t off = (uint32_t)(wn + nb * 16 + b_r) * (BKP * 2) + ks * 32 + b_kc * 16;
                uint32_t t[4];
                ldsm4(t, uBH + (uint32_t)b * BBB + off);
                bh[2 * nb][0] = t[0]; bh[2 * nb][1] = t[1];
                bh[2 * nb + 1][0] = t[2]; bh[2 * nb + 1][1] = t[3];
            }
            #pragma unroll
            for (int mf = 0; mf < MF; mf++)
                #pragma unroll
                for (int nf = 0; nf < NF; nf++) {
                    mma_f16(acc[mf][nf], ah[mf], bh[nf]);
                    mma_f16(acc[mf][nf], al[mf], bh[nf]);
                }
        }
        if (i + 1 < nit) storeA(b ^ 1);
    }

    gemm_epilogue<MF, BN, NF, RELU, BIAS>(acc, bias, C, M, blockM, wm, wn, lane);
}

// ===== 3-term fp32-A GEMM (logits) =====
template<int BN, bool RELU, bool BIAS>
__global__ void __launch_bounds__(256, 2)
mma_gemm_f32(const float* __restrict__ A,
             const __half* __restrict__ Bhi, const __half* __restrict__ Blo,
             const float* __restrict__ bias, float* __restrict__ C,
             int M, int K)
{
    constexpr int BM = 128, BK = 32;
    constexpr int MF = 4;
    constexpr int WN = BN / 4;
    constexpr int NF = WN / 8;
    constexpr int ASZ = BM * BKP;
    constexpr int BBB = BN * BKP * 2;

    extern __shared__ __half smh[];
    __half* AHp = smh;
    __half* ALp = smh + 2 * ASZ;
    const uint32_t sb  = smem_to_u32(smh);
    const uint32_t uAH = sb;
    const uint32_t uAL = sb + 2 * AB_BYTES;
    const uint32_t uBH = sb + 4 * AB_BYTES;
    const uint32_t uBL = sb + 4 * AB_BYTES + 2 * BBB;

    const int tid  = threadIdx.x;
    const int lane = tid & 31;
    const int wid  = tid >> 5;
    const int wm   = (wid >> 2) * 64;
    const int wn   = (wid & 3) * WN;
    const int blockM = blockIdx.x * BM;

    const int a_r  = lane & 15, a_kc = lane >> 4;
    const int b_r  = (lane & 7) + ((lane >> 4) << 3);
    const int b_kc = (lane >> 3) & 1;

    float acc[MF][NF][4];
    #pragma unroll
    for (int mf = 0; mf < MF; mf++)
        #pragma unroll
        for (int nf = 0; nf < NF; nf++)
            #pragma unroll
            for (int q = 0; q < 4; q++) acc[mf][nf][q] = 0.0f;

    const int nit = K / BK;

    auto fillB = [&](int i, int b) {
        constexpr int CH = BN * 4;
        #pragma unroll
        for (int it = 0; it < (CH + 255) / 256; it++) {
            int id = tid + it * 256;
            if (CH % 256 == 0 || id < CH) {
                int n = id >> 2, c = id & 3;
                uint32_t off = (uint32_t)b * BBB + (uint32_t)n * (BKP * 2) + c * 16;
                cp_async16(uBH + off, Bhi + (size_t)n * K + i * BK + c * 8);
                cp_async16(uBL + off, Blo + (size_t)n * K + i * BK + c * 8);
            }
        }
    };
    float4 aR[4];
    auto loadA = [&](int i) {
        #pragma unroll
        for (int it = 0; it < 4; it++) {
            int id  = tid + it * 256;
            int row = id >> 3, c4 = id & 7;
            int gr  = blockM + row;
            float4 v = make_float4(0.f, 0.f, 0.f, 0.f);
            if (gr < M)
                v = *(const float4*)(A + (size_t)gr * K + i * BK + c4 * 4);
            aR[it] = v;
        }
    };
    auto storeA = [&](int b) {
        #pragma unroll
        for (int it = 0; it < 4; it++) {
            int id  = tid + it * 256;
            int row = id >> 3, c4 = id & 7;
            float4 v = aR[it];
            __half hx, lx, hy, ly, hz, lz, hw, lw;
            split_f16(v.x, hx, lx); split_f16(v.y, hy, ly);
            split_f16(v.z, hz, lz); split_f16(v.w, hw, lw);
            int off = b * ASZ + row * BKP + c4 * 4;
            ((half2*)(AHp + off))[0] = __halves2half2(hx, hy);
            ((half2*)(AHp + off))[1] = __halves2half2(hz, hw);
            ((half2*)(ALp + off))[0] = __halves2half2(lx, ly);
            ((half2*)(ALp + off))[1] = __halves2half2(lz, lw);
        }
    };

    loadA(0);
    storeA(0);
    fillB(0, 0);
    cp_commit();

    for (int i = 0; i < nit; i++) {
        const int b = i & 1;
        cp_wait<0>();
        __syncthreads();
        if (i + 1 < nit) {
            fillB(i + 1, b ^ 1);
            cp_commit();
            loadA(i + 1);
        }
        gemm_compute<MF, NF, 2, AB_BYTES, BBB, BKP * 2>(
            uAH, uAL, uBH, uBL, b, wm, wn, a_r, a_kc, b_r, b_kc, acc);
        if (i + 1 < nit) storeA(b ^ 1);
    }

    gemm_epilogue<MF, BN, NF, RELU, BIAS>(acc, bias, C, M, blockM, wm, wn, lane);
}

// ===== 3-term pre-split fp16 A GEMM (convs) =====
template<int BN>
__global__ void __launch_bounds__(256, 2)
mma_gemm_f16(const __half* __restrict__ Ahi, const __half* __restrict__ Alo,
             const __half* __restrict__ Bhi, const __half* __restrict__ Blo,
             float* __restrict__ C, int M, int K)
{
    constexpr int BM = 128, BK = 32;
    constexpr int MF = 4;
    constexpr int WN = BN / 4;
    constexpr int NF = WN / 8;
    constexpr int BBB = BN * BKP * 2;

    extern __shared__ __half smh[];
    const uint32_t sb  = smem_to_u32(smh);
    const uint32_t uAH = sb;
    const uint32_t uAL = sb + 2 * AB_BYTES;
    const uint32_t uBH = sb + 4 * AB_BYTES;
    const uint32_t uBL = sb + 4 * AB_BYTES + 2 * BBB;

    const int tid  = threadIdx.x;
    const int lane = tid & 31;
    const int wid  = tid >> 5;
    const int wm   = (wid >> 2) * 64;
    const int wn   = (wid & 3) * WN;
    const int blockM = blockIdx.x * BM;

    const int a_r  = lane & 15, a_kc = lane >> 4;
    const int b_r  = (lane & 7) + ((lane >> 4) << 3);
    const int b_kc = (lane >> 3) & 1;

    float acc[MF][NF][4];
    #pragma unroll
    for (int mf = 0; mf < MF; mf++)
        #pragma unroll
        for (int nf = 0; nf < NF; nf++)
            #pragma unroll
            for (int q = 0; q < 4; q++) acc[mf][nf][q] = 0.0f;

    const int nit = K / BK;

    auto fillA = [&](int i, int b) {
        constexpr int CH = BM * 4;
        #pragma unroll
        for (int it = 0; it < CH / 256; it++) {
            int id = tid + it * 256;
            int row = id >> 2, c = id & 3;
            int gr = blockM + row;
            if (gr < M) {
                uint32_t off = (uint32_t)b * AB_BYTES + (uint32_t)row * (BKP * 2) + c * 16;
                cp_async16(uAH + off, Ahi + (size_t)gr * K + i * BK + c * 8);
                cp_async16(uAL + off, Alo + (size_t)gr * K + i * BK + c * 8);
            }
        }
    };
    auto fillB = [&](int i, int b) {
        constexpr int CH = BN * 4;
        #pragma unroll
        for (int it = 0; it < (CH + 255) / 256; it++) {
            int id = tid + it * 256;
            if (CH % 256 == 0 || id < CH) {
                int n = id >> 2, c = id & 3;
                uint32_t off = (uint32_t)b * BBB + (uint32_t)n * (BKP * 2) + c * 16;
                cp_async16(uBH + off, Bhi + (size_t)n * K + i * BK + c * 8);
                cp_async16(uBL + off, Blo + (size_t)n * K + i * BK + c * 8);
            }
        }
    };

    fillA(0, 0);
    fillB(0, 0);
    cp_commit();

    for (int i = 0; i < nit; i++) {
        const int b = i & 1;
        cp_wait<0>();
        __syncthreads();
        if (i + 1 < nit) {
            fillA(i + 1, b ^ 1);
            fillB(i + 1, b ^ 1);
            cp_commit();
        }
        gemm_compute<MF, NF, 2, AB_BYTES, BBB, BKP * 2>(
            uAH, uAL, uBH, uBL, b, wm, wn, a_r, a_kc, b_r, b_kc, acc);
    }

    gemm_epilogue<MF, BN, NF, false, false>(acc, nullptr, C, M, blockM, wm, wn, lane);
}

// ---------------- launch ----------------
extern "C" void kernel_launch(void* const* d_in, const int* in_sizes, int n_in,
                              void* d_out, int out_size)
{
    const float* x  = (const float*)d_in[0];
    const int*   ei = (const int*)  d_in[1];
    const float* w1 = (const float*)d_in[2];
    const float* b1 = (const float*)d_in[3];
    const float* cw = (const float*)d_in[4];
    const float* w2 = (const float*)d_in[5];
    const float* b2 = (const float*)d_in[6];

    float* out    = (float*)d_out;
    float* hout   = out;
    float* logits = out + (size_t)NN * HD;

    float *p_h0, *p_h;
    __half *p_chi, *p_clo;
    __half *p_w1h, *p_w1l, *p_cwh, *p_cwl, *p_w2h, *p_w2l;
    cudaGetSymbolAddress((void**)&p_h0,  g_h0);
    cudaGetSymbolAddress((void**)&p_h,   g_h);
    cudaGetSymbolAddress((void**)&p_chi, g_comb_hi);
    cudaGetSymbolAddress((void**)&p_clo, g_comb_lo);
    cudaGetSymbolAddress((void**)&p_w1h, g_w1t_hi);
    cudaGetSymbolAddress((void**)&p_w1l, g_w1t_lo);
    cudaGetSymbolAddress((void**)&p_cwh, g_cwt_hi);
    cudaGetSymbolAddress((void**)&p_cwl, g_cwt_lo);
    cudaGetSymbolAddress((void**)&p_w2h, g_w2t_hi);
    cudaGetSymbolAddress((void**)&p_w2l, g_w2t_lo);

    const int TPB = 256;
    const int gemm_grid = (NN + 127) / 128;                    // 782
    const int NBLK = (NN + 1023) / 1024;                       // 98
    const int SMEM_2T  = 4 * AB_BYTES + 2 * 128 * BKP * 2;     // 61440 B
    const int SMEM_128 = 4 * AB_BYTES + 4 * 128 * BKP * 2;     // 81920 B
    const int SMEM_64  = 4 * AB_BYTES + 4 * 64 * BKP * 2;      // 61440 B

    cudaFuncSetAttribute(mma_gemm_f32_2t<128, true, true>,
                         cudaFuncAttributeMaxDynamicSharedMemorySize, SMEM_2T);
    cudaFuncSetAttribute(mma_gemm_f16<128>,
                         cudaFuncAttributeMaxDynamicSharedMemorySize, SMEM_128);
    cudaFuncSetAttribute(mma_gemm_f32<64, false, true>,
                         cudaFuncAttributeMaxDynamicSharedMemorySize, SMEM_64);

    // launches 1-3, then gemm1 as launch #4 (profiler capture slot)
    cnt_init_kernel <<<(NN + TPB - 1) / TPB, TPB>>>();
    cnt_accum_kernel<<<(NE + TPB - 1) / TPB, TPB>>>(ei);
    prep_weights    <<<(HD*DIN + 2*HD*HD + DOUT*HD + TPB - 1) / TPB, TPB>>>(w1, cw, w2);

    // h0 = relu(x @ w1h + b1), A kept exact via hi+lo  [launch #4 -> profiled]
    mma_gemm_f32_2t<128, true, true><<<gemm_grid, 256, SMEM_2T>>>(
        x, p_w1h, b1, p_h0, NN, DIN);

    // rest of CSR build
    scan1_kernel    <<<NBLK, 1024>>>();
    scan2_kernel    <<<1, 128>>>(NBLK);
    fin_kernel      <<<(NN + TPB - 1) / TPB, TPB>>>();
    scatter_kernel  <<<(NE + TPB - 1) / TPB, TPB>>>(ei);

    // ---- layer 1 ----
    agg_kernel<<<(NN * 32 + TPB - 1) / TPB, TPB>>>(p_h0);
    mma_gemm_f16<128><<<gemm_grid, 256, SMEM_128>>>(
        p_chi, p_clo, p_cwh, p_cwl, p_h, NN, HD);

    // ---- layer 2 (writes h directly to d_out) ----
    agg_kernel<<<(NN * 32 + TPB - 1) / TPB, TPB>>>(p_h);
    mma_gemm_f16<128><<<gemm_grid, 256, SMEM_128>>>(
        p_chi, p_clo, p_cwh + HD * HD, p_cwl + HD * HD, hout, NN, HD);

    // logits = hout @ w2 + b2
    mma_gemm_f32<64, false, true><<<gemm_grid, 256, SMEM_64>>>(
        hout, p_w2h, p_w2l, b2, logits, NN, HD);
}

// round 14
// speedup vs baseline: 1.3733x; 1.2133x over previous
#include <cuda_runtime.h>
#include <cuda_fp16.h>
#include <cstdint>

#define NN   100000
#define NE   1600000
#define DIN  512
#define HD   128
#define DOUT 64

// ---------------- scratch (device globals: allocation-free) ----------------
__device__ float g_deg[NN];                     // dinv
__device__ float g_h0 [(size_t)NN * HD];
__device__ float g_h  [(size_t)NN * HD];
__device__ __half g_comb[(size_t)NN * HD];      // combined residual input, fp16
// CSR build
__device__ int g_cnt[NN];
__device__ int g_rp [NN + 1];
__device__ int g_cur[NN];
__device__ int g_csr[NE];
__device__ int g_bsum[128], g_boff[128];
// K-major fp16 weights: [N][K]
__device__ __half g_w1t[HD * DIN];
__device__ __half g_cwt[2 * HD * HD];
__device__ __half g_w2t[DOUT * HD];

// ======================= helpers =====================
__device__ __forceinline__ uint32_t smem_to_u32(const void* p) {
    uint32_t a;
    asm("{ .reg .u64 t; cvta.to.shared.u64 t, %1; cvt.u32.u64 %0, t; }" : "=r"(a) : "l"(p));
    return a;
}
__device__ __forceinline__ void ldsm4(uint32_t* r, uint32_t addr) {
    asm volatile("ldmatrix.sync.aligned.m8n8.x4.shared.b16 {%0,%1,%2,%3}, [%4];"
                 : "=r"(r[0]), "=r"(r[1]), "=r"(r[2]), "=r"(r[3]) : "r"(addr));
}
__device__ __forceinline__ void mma_f16(float* c, const uint32_t* a, const uint32_t* b) {
    asm volatile("mma.sync.aligned.m16n8k16.row.col.f32.f16.f16.f32 "
                 "{%0,%1,%2,%3}, {%4,%5,%6,%7}, {%8,%9}, {%0,%1,%2,%3};"
                 : "+f"(c[0]), "+f"(c[1]), "+f"(c[2]), "+f"(c[3])
                 : "r"(a[0]), "r"(a[1]), "r"(a[2]), "r"(a[3]), "r"(b[0]), "r"(b[1]));
}
__device__ __forceinline__ void cp_async16(uint32_t dst, const void* src) {
    asm volatile("cp.async.cg.shared.global [%0], [%1], 16;"
                 :: "r"(dst), "l"((unsigned long long)__cvta_generic_to_global(src)) : "memory");
}
__device__ __forceinline__ void cp_commit() {
    asm volatile("cp.async.commit_group;" ::: "memory");
}
template<int N> __device__ __forceinline__ void cp_wait() {
    asm volatile("cp.async.wait_group %0;" :: "n"(N) : "memory");
}

// ---------------- CSR build ----------------
__global__ void cnt_init_kernel() {
    int i = blockIdx.x * blockDim.x + threadIdx.x;
    if (i < NN) g_cnt[i] = 0;
}
__global__ void cnt_accum_kernel(const int* __restrict__ ei) {
    int e = blockIdx.x * blockDim.x + threadIdx.x;
    if (e < NE) atomicAdd(&g_cnt[ei[NE + e]], 1);
}
__global__ void scan1_kernel() {      // 98 blocks x 1024
    __shared__ int s[1024];
    int t = threadIdx.x;
    int i = blockIdx.x * 1024 + t;
    int x = (i < NN) ? g_cnt[i] : 0;
    s[t] = x;
    __syncthreads();
    #pragma unroll
    for (int off = 1; off < 1024; off <<= 1) {
        int v = (t >= off) ? s[t - off] : 0;
        __syncthreads();
        s[t] += v;
        __syncthreads();
    }
    if (i < NN) g_rp[i] = s[t] - x;
    if (t == 1023) g_bsum[blockIdx.x] = s[1023];
}
__global__ void scan2_kernel(int nblk) {
    __shared__ int s[128];
    int t = threadIdx.x;
    int v = (t < nblk) ? g_bsum[t] : 0;
    s[t] = v;
    __syncthreads();
    #pragma unroll
    for (int off = 1; off < 128; off <<= 1) {
        int u = (t >= off) ? s[t - off] : 0;
        __syncthreads();
        s[t] += u;
        __syncthreads();
    }
    if (t < nblk) g_boff[t] = s[t] - v;
}
__global__ void fin_kernel() {
    int i = blockIdx.x * blockDim.x + threadIdx.x;
    if (i >= NN) return;
    int rp = g_rp[i] + g_boff[i >> 10];
    g_rp[i] = rp;
    g_cur[i] = rp;
    g_deg[i] = rsqrtf(1.0f + (float)g_cnt[i]);
    if (i == 0) g_rp[NN] = NE;
}
__global__ void scatter_kernel(const int* __restrict__ ei) {
    int e = blockIdx.x * blockDim.x + threadIdx.x;
    if (e >= NE) return;
    int c = ei[NE + e];
    int slot = atomicAdd(&g_cur[c], 1);
    g_csr[slot] = ei[e];
}

// ------- aggregation + residual combine + fp16 round, warp per node --------
__global__ void agg_kernel(const float* __restrict__ src) {
    int gid  = blockIdx.x * blockDim.x + threadIdx.x;
    int node = gid >> 5;
    if (node >= NN) return;
    int lane = gid & 31;
    const float4* s4 = (const float4*)src;
    float dn = g_deg[node];
    float4 acc = s4[(size_t)node * 32 + lane];
    float w0 = dn * dn;
    acc.x *= w0; acc.y *= w0; acc.z *= w0; acc.w *= w0;
    int j   = g_rp[node];
    int end = g_rp[node + 1];
    for (; j + 7 < end; j += 8) {
        int   si[8];
        float qi[8];
        float4 vi[8];
        #pragma unroll
        for (int u = 0; u < 8; u++) si[u] = g_csr[j + u];
        #pragma unroll
        for (int u = 0; u < 8; u++) qi[u] = dn * g_deg[si[u]];
        #pragma unroll
        for (int u = 0; u < 8; u++) vi[u] = s4[(size_t)si[u] * 32 + lane];
        #pragma unroll
        for (int u = 0; u < 8; u++) {
            acc.x += qi[u] * vi[u].x;
            acc.y += qi[u] * vi[u].y;
            acc.z += qi[u] * vi[u].z;
            acc.w += qi[u] * vi[u].w;
        }
    }
    for (; j + 3 < end; j += 4) {
        int s0 = g_csr[j],     s1 = g_csr[j + 1];
        int s2 = g_csr[j + 2], s3 = g_csr[j + 3];
        float q0 = dn * g_deg[s0], q1 = dn * g_deg[s1];
        float q2 = dn * g_deg[s2], q3 = dn * g_deg[s3];
        float4 v0 = s4[(size_t)s0 * 32 + lane];
        float4 v1 = s4[(size_t)s1 * 32 + lane];
        float4 v2 = s4[(size_t)s2 * 32 + lane];
        float4 v3 = s4[(size_t)s3 * 32 + lane];
        acc.x += q0 * v0.x + q1 * v1.x + q2 * v2.x + q3 * v3.x;
        acc.y += q0 * v0.y + q1 * v1.y + q2 * v2.y + q3 * v3.y;
        acc.z += q0 * v0.z + q1 * v1.z + q2 * v2.z + q3 * v3.z;
        acc.w += q0 * v0.w + q1 * v1.w + q2 * v2.w + q3 * v3.w;
    }
    for (; j < end; j++) {
        int sa = g_csr[j];
        float wa = dn * g_deg[sa];
        float4 va = s4[(size_t)sa * 32 + lane];
        acc.x += wa * va.x; acc.y += wa * va.y;
        acc.z += wa * va.z; acc.w += wa * va.w;
    }
    float4 h0v = ((const float4*)g_h0)[(size_t)node * 32 + lane];
    float cx = 0.9f * acc.x + 0.1f * h0v.x;
    float cy = 0.9f * acc.y + 0.1f * h0v.y;
    float cz = 0.9f * acc.z + 0.1f * h0v.z;
    float cw = 0.9f * acc.w + 0.1f * h0v.w;
    half2* ph = (half2*)(g_comb + (size_t)node * HD) + lane * 2;
    ph[0] = __halves2half2(__float2half_rn(cx), __float2half_rn(cy));
    ph[1] = __halves2half2(__float2half_rn(cz), __float2half_rn(cw));
}

// ---------------- weight transpose + fp16 round ----------------
__global__ void prep_weights(const float* __restrict__ w1,
                             const float* __restrict__ cw,
                             const float* __restrict__ w2) {
    int i = blockIdx.x * blockDim.x + threadIdx.x;
    const int N1 = HD * DIN;
    const int N2 = 2 * HD * HD;
    const int N3 = DOUT * HD;
    if (i < N1) {
        int n = i / DIN, k = i % DIN;
        g_w1t[i] = __float2half_rn(w1[(size_t)k * HD + n]);
    } else if (i < N1 + N2) {
        int j = i - N1;
        int l = j / (HD * HD), r = j % (HD * HD);
        int n = r / HD, k = r % HD;
        g_cwt[j] = __float2half_rn(cw[(size_t)l * HD * HD + (size_t)k * HD + n]);
    } else if (i < N1 + N2 + N3) {
        int j = i - N1 - N2;
        int n = j / HD, k = j % HD;
        g_w2t[j] = __float2half_rn(w2[(size_t)k * DOUT + n]);
    }
}

// ======== shared GEMM pieces (BM=128, BK=32, 8 warps, 2 CTAs/SM) ========
#define BKP 40
#define AB_BYTES (128 * BKP * 2)

// single-term fp16 compute
template<int MF, int NF, int NKS, int ABB, int BBB, int BKPB>
__device__ __forceinline__ void gemm_compute_1t(
    uint32_t uA, uint32_t uB,
    int b, int wm, int wn, int a_r, int a_kc, int b_r, int b_kc,
    float (*acc)[NF][4])
{
    #pragma unroll
    for (int ks = 0; ks < NKS; ks++) {
        uint32_t ah[MF][4];
        #pragma unroll
        for (int mf = 0; mf < MF; mf++) {
            uint32_t off = (uint32_t)(wm + mf * 16 + a_r) * BKPB + ks * 32 + a_kc * 16;
            ldsm4(ah[mf], uA + (uint32_t)b * ABB + off);
        }
        uint32_t bh[NF][2];
        #pragma unroll
        for (int nb = 0; nb < NF / 2; nb++) {
            uint32_t off = (uint32_t)(wn + nb * 16 + b_r) * BKPB + ks * 32 + b_kc * 16;
            uint32_t t[4];
            ldsm4(t, uB + (uint32_t)b * BBB + off);
            bh[2 * nb][0] = t[0]; bh[2 * nb][1] = t[1];
            bh[2 * nb + 1][0] = t[2]; bh[2 * nb + 1][1] = t[3];
        }
        #pragma unroll
        for (int mf = 0; mf < MF; mf++)
            #pragma unroll
            for (int nf = 0; nf < NF; nf++)
                mma_f16(acc[mf][nf], ah[mf], bh[nf]);
    }
}

template<int MF, int BN, int NF, bool RELU, bool BIAS>
__device__ __forceinline__ void gemm_epilogue(
    float (*acc)[NF][4], const float* bias, float* C,
    int M, int blockM, int wm, int wn, int lane)
{
    #pragma unroll
    for (int mf = 0; mf < MF; mf++) {
        int row0 = blockM + wm + mf * 16 + (lane >> 2);
        #pragma unroll
        for (int nf = 0; nf < NF; nf++) {
            int col = wn + nf * 8 + (lane & 3) * 2;
            float2 v0 = make_float2(acc[mf][nf][0], acc[mf][nf][1]);
            float2 v1 = make_float2(acc[mf][nf][2], acc[mf][nf][3]);
            if (BIAS) {
                float b0 = bias[col], b1 = bias[col + 1];
                v0.x += b0; v0.y += b1;
                v1.x += b0; v1.y += b1;
            }
            if (RELU) {
                v0.x = fmaxf(v0.x, 0.f); v0.y = fmaxf(v0.y, 0.f);
                v1.x = fmaxf(v1.x, 0.f); v1.y = fmaxf(v1.y, 0.f);
            }
            if (row0 < M)     *(float2*)(C + (size_t)row0 * BN + col)       = v0;
            if (row0 + 8 < M) *(float2*)(C + (size_t)(row0 + 8) * BN + col) = v1;
        }
    }
}

// ===== fp32-A single-term GEMM (gemm1, logits): C = fp16(A) @ Bh^T =====
template<int BN, bool RELU, bool BIAS>
__global__ void __launch_bounds__(256, 2)
mma_gemm_f32_1t(const float* __restrict__ A,
                const __half* __restrict__ Bh,
                const float* __restrict__ bias, float* __restrict__ C,
                int M, int K)
{
    constexpr int BM = 128, BK = 32;
    constexpr int MF = 4;
    constexpr int WN = BN / 4;
    constexpr int NF = WN / 8;
    constexpr int ASZ = BM * BKP;
    constexpr int BBB = BN * BKP * 2;

    extern __shared__ __half smh[];
    __half* Ap = smh;                       // [2][ASZ]
    const uint32_t sb = smem_to_u32(smh);
    const uint32_t uA = sb;
    const uint32_t uB = sb + 2 * AB_BYTES;

    const int tid  = threadIdx.x;
    const int lane = tid & 31;
    const int wid  = tid >> 5;
    const int wm   = (wid >> 2) * 64;
    const int wn   = (wid & 3) * WN;
    const int blockM = blockIdx.x * BM;

    const int a_r  = lane & 15, a_kc = lane >> 4;
    const int b_r  = (lane & 7) + ((lane >> 4) << 3);
    const int b_kc = (lane >> 3) & 1;

    float acc[MF][NF][4];
    #pragma unroll
    for (int mf = 0; mf < MF; mf++)
        #pragma unroll
        for (int nf = 0; nf < NF; nf++)
            #pragma unroll
            for (int q = 0; q < 4; q++) acc[mf][nf][q] = 0.0f;

    const int nit = K / BK;

    auto fillB = [&](int i, int b) {
        constexpr int CH = BN * 4;
        #pragma unroll
        for (int it = 0; it < (CH + 255) / 256; it++) {
            int id = tid + it * 256;
            if (CH % 256 == 0 || id < CH) {
                int n = id >> 2, c = id & 3;
                uint32_t off = (uint32_t)b * BBB + (uint32_t)n * (BKP * 2) + c * 16;
                cp_async16(uB + off, Bh + (size_t)n * K + i * BK + c * 8);
            }
        }
    };
    float4 aR[4];
    auto loadA = [&](int i) {
        #pragma unroll
        for (int it = 0; it < 4; it++) {
            int id  = tid + it * 256;
            int row = id >> 3, c4 = id & 7;
            int gr  = blockM + row;
            float4 v = make_float4(0.f, 0.f, 0.f, 0.f);
            if (gr < M)
                v = *(const float4*)(A + (size_t)gr * K + i * BK + c4 * 4);
            aR[it] = v;
        }
    };
    auto storeA = [&](int b) {
        #pragma unroll
        for (int it = 0; it < 4; it++) {
            int id  = tid + it * 256;
            int row = id >> 3, c4 = id & 7;
            float4 v = aR[it];
            int off = b * ASZ + row * BKP + c4 * 4;
            ((half2*)(Ap + off))[0] =
                __halves2half2(__float2half_rn(v.x), __float2half_rn(v.y));
            ((half2*)(Ap + off))[1] =
                __halves2half2(__float2half_rn(v.z), __float2half_rn(v.w));
        }
    };

    loadA(0);
    storeA(0);
    fillB(0, 0);
    cp_commit();

    for (int i = 0; i < nit; i++) {
        const int b = i & 1;
        cp_wait<0>();
        __syncthreads();
        if (i + 1 < nit) {
            fillB(i + 1, b ^ 1);
            cp_commit();
            loadA(i + 1);
        }
        gemm_compute_1t<MF, NF, 2, AB_BYTES, BBB, BKP * 2>(
            uA, uB, b, wm, wn, a_r, a_kc, b_r, b_kc, acc);
        if (i + 1 < nit) storeA(b ^ 1);
    }

    gemm_epilogue<MF, BN, NF, RELU, BIAS>(acc, bias, C, M, blockM, wm, wn, lane);
}

// ===== fp16-A single-term GEMM (convs): pure cp.async both sides =====
template<int BN>
__global__ void __launch_bounds__(256, 2)
mma_gemm_f16_1t(const __half* __restrict__ Ah,
                const __half* __restrict__ Bh,
                float* __restrict__ C, int M, int K)
{
    constexpr int BM = 128, BK = 32;
    constexpr int MF = 4;
    constexpr int WN = BN / 4;
    constexpr int NF = WN / 8;
    constexpr int BBB = BN * BKP * 2;

    extern __shared__ __half smh[];
    const uint32_t sb = smem_to_u32(smh);
    const uint32_t uA = sb;
    const uint32_t uB = sb + 2 * AB_BYTES;

    const int tid  = threadIdx.x;
    const int lane = tid & 31;
    const int wid  = tid >> 5;
    const int wm   = (wid >> 2) * 64;
    const int wn   = (wid & 3) * WN;
    const int blockM = blockIdx.x * BM;

    const int a_r  = lane & 15, a_kc = lane >> 4;
    const int b_r  = (lane & 7) + ((lane >> 4) << 3);
    const int b_kc = (lane >> 3) & 1;

    float acc[MF][NF][4];
    #pragma unroll
    for (int mf = 0; mf < MF; mf++)
        #pragma unroll
        for (int nf = 0; nf < NF; nf++)
            #pragma unroll
            for (int q = 0; q < 4; q++) acc[mf][nf][q] = 0.0f;

    const int nit = K / BK;

    auto fillA = [&](int i, int b) {
        constexpr int CH = BM * 4;
        #pragma unroll
        for (int it = 0; it < CH / 256; it++) {
            int id = tid + it * 256;
            int row = id >> 2, c = id & 3;
            int gr = blockM + row;
            if (gr < M) {
                uint32_t off = (uint32_t)b * AB_BYTES + (uint32_t)row * (BKP * 2) + c * 16;
                cp_async16(uA + off, Ah + (size_t)gr * K + i * BK + c * 8);
            }
        }
    };
    auto fillB = [&](int i, int b) {
        constexpr int CH = BN * 4;
        #pragma unroll
        for (int it = 0; it < (CH + 255) / 256; it++) {
            int id = tid + it * 256;
            if (CH % 256 == 0 || id < CH) {
                int n = id >> 2, c = id & 3;
                uint32_t off = (uint32_t)b * BBB + (uint32_t)n * (BKP * 2) + c * 16;
                cp_async16(uB + off, Bh + (size_t)n * K + i * BK + c * 8);
            }
        }
    };

    fillA(0, 0);
    fillB(0, 0);
    cp_commit();

    for (int i = 0; i < nit; i++) {
        const int b = i & 1;
        cp_wait<0>();
        __syncthreads();
        if (i + 1 < nit) {
            fillA(i + 1, b ^ 1);
            fillB(i + 1, b ^ 1);
            cp_commit();
        }
        gemm_compute_1t<MF, NF, 2, AB_BYTES, BBB, BKP * 2>(
            uA, uB, b, wm, wn, a_r, a_kc, b_r, b_kc, acc);
    }

    gemm_epilogue<MF, BN, NF, false, false>(acc, nullptr, C, M, blockM, wm, wn, lane);
}

// ---------------- launch ----------------
extern "C" void kernel_launch(void* const* d_in, const int* in_sizes, int n_in,
                              void* d_out, int out_size)
{
    const float* x  = (const float*)d_in[0];
    const int*   ei = (const int*)  d_in[1];
    const float* w1 = (const float*)d_in[2];
    const float* b1 = (const float*)d_in[3];
    const float* cw = (const float*)d_in[4];
    const float* w2 = (const float*)d_in[5];
    const float* b2 = (const float*)d_in[6];

    float* out    = (float*)d_out;
    float* hout   = out;
    float* logits = out + (size_t)NN * HD;

    float *p_h0, *p_h;
    __half *p_comb, *p_w1t, *p_cwt, *p_w2t;
    cudaGetSymbolAddress((void**)&p_h0,   g_h0);
    cudaGetSymbolAddress((void**)&p_h,    g_h);
    cudaGetSymbolAddress((void**)&p_comb, g_comb);
    cudaGetSymbolAddress((void**)&p_w1t,  g_w1t);
    cudaGetSymbolAddress((void**)&p_cwt,  g_cwt);
    cudaGetSymbolAddress((void**)&p_w2t,  g_w2t);

    const int TPB = 256;
    const int gemm_grid = (NN + 127) / 128;                    // 782
    const int NBLK = (NN + 1023) / 1024;                       // 98
    const int SMEM_G1  = 2 * AB_BYTES + 2 * 128 * BKP * 2;     // 40960 B
    const int SMEM_CV  = 2 * AB_BYTES + 2 * 128 * BKP * 2;     // 40960 B
    const int SMEM_LG  = 2 * AB_BYTES + 2 * 64 * BKP * 2;      // 30720 B

    cudaFuncSetAttribute(mma_gemm_f32_1t<128, true, true>,
                         cudaFuncAttributeMaxDynamicSharedMemorySize, SMEM_G1);
    cudaFuncSetAttribute(mma_gemm_f16_1t<128>,
                         cudaFuncAttributeMaxDynamicSharedMemorySize, SMEM_CV);
    cudaFuncSetAttribute(mma_gemm_f32_1t<64, false, true>,
                         cudaFuncAttributeMaxDynamicSharedMemorySize, SMEM_LG);

    // launches 1-3, then gemm1 as launch #4 (profiler capture slot)
    cnt_init_kernel <<<(NN + TPB - 1) / TPB, TPB>>>();
    cnt_accum_kernel<<<(NE + TPB - 1) / TPB, TPB>>>(ei);
    prep_weights    <<<(HD*DIN + 2*HD*HD + DOUT*HD + TPB - 1) / TPB, TPB>>>(w1, cw, w2);

    // h0 = relu(fp16(x) @ fp16(w1) + b1)   [launch #4 -> profiled]
    mma_gemm_f32_1t<128, true, true><<<gemm_grid, 256, SMEM_G1>>>(
        x, p_w1t, b1, p_h0, NN, DIN);

    // rest of CSR build
    scan1_kernel    <<<NBLK, 1024>>>();
    scan2_kernel    <<<1, 128>>>(NBLK);
    fin_kernel      <<<(NN + TPB - 1) / TPB, TPB>>>();
    scatter_kernel  <<<(NE + TPB - 1) / TPB, TPB>>>(ei);

    // ---- layer 1 ----
    agg_kernel<<<(NN * 32 + TPB - 1) / TPB, TPB>>>(p_h0);
    mma_gemm_f16_1t<128><<<gemm_grid, 256, SMEM_CV>>>(
        p_comb, p_cwt, p_h, NN, HD);

    // ---- layer 2 (writes h directly to d_out) ----
    agg_kernel<<<(NN * 32 + TPB - 1) / TPB, TPB>>>(p_h);
    mma_gemm_f16_1t<128><<<gemm_grid, 256, SMEM_CV>>>(
        p_comb, p_cwt + HD * HD, hout, NN, HD);

    // logits = hout @ w2 + b2
    mma_gemm_f32_1t<64, false, true><<<gemm_grid, 256, SMEM_LG>>>(
        hout, p_w2t, b2, logits, NN, HD);
}

// round 16
// speedup vs baseline: 1.4610x; 1.0638x over previous
#include <cuda_runtime.h>
#include <cuda_fp16.h>
#include <cstdint>

#define NN   100000
#define NE   1600000
#define DIN  512
#define HD   128
#define DOUT 64

// ---------------- scratch (device globals: allocation-free) ----------------
__device__ float  g_deg[NN];                    // dinv
__device__ __half g_h0h[(size_t)NN * HD];       // h0, fp16 (gather source + residual)
__device__ __half g_hh [(size_t)NN * HD];       // h (layer-1 out), fp16 (gather source)
__device__ __half g_comb[(size_t)NN * HD];      // combined residual input, fp16
// CSR build
__device__ int g_cnt[NN];
__device__ int g_rp [NN + 1];
__device__ int g_cur[NN];
__device__ int g_csr[NE];
__device__ int g_bsum[128], g_boff[128];
// K-major fp16 weights: [N][K]
__device__ __half g_w1t[HD * DIN];
__device__ __half g_cwt[2 * HD * HD];
__device__ __half g_w2t[DOUT * HD];

// ======================= helpers =====================
__device__ __forceinline__ uint32_t smem_to_u32(const void* p) {
    uint32_t a;
    asm("{ .reg .u64 t; cvta.to.shared.u64 t, %1; cvt.u32.u64 %0, t; }" : "=r"(a) : "l"(p));
    return a;
}
__device__ __forceinline__ void ldsm4(uint32_t* r, uint32_t addr) {
    asm volatile("ldmatrix.sync.aligned.m8n8.x4.shared.b16 {%0,%1,%2,%3}, [%4];"
                 : "=r"(r[0]), "=r"(r[1]), "=r"(r[2]), "=r"(r[3]) : "r"(addr));
}
__device__ __forceinline__ void mma_f16(float* c, const uint32_t* a, const uint32_t* b) {
    asm volatile("mma.sync.aligned.m16n8k16.row.col.f32.f16.f16.f32 "
                 "{%0,%1,%2,%3}, {%4,%5,%6,%7}, {%8,%9}, {%0,%1,%2,%3};"
                 : "+f"(c[0]), "+f"(c[1]), "+f"(c[2]), "+f"(c[3])
                 : "r"(a[0]), "r"(a[1]), "r"(a[2]), "r"(a[3]), "r"(b[0]), "r"(b[1]));
}
__device__ __forceinline__ void cp_async16(uint32_t dst, const void* src) {
    asm volatile("cp.async.cg.shared.global [%0], [%1], 16;"
                 :: "r"(dst), "l"((unsigned long long)__cvta_generic_to_global(src)) : "memory");
}
__device__ __forceinline__ void cp_commit() {
    asm volatile("cp.async.commit_group;" ::: "memory");
}
template<int N> __device__ __forceinline__ void cp_wait() {
    asm volatile("cp.async.wait_group %0;" :: "n"(N) : "memory");
}
__device__ __forceinline__ float4 h4_to_f4(uint2 v) {
    float2 fa = __half22float2(*(half2*)&v.x);
    float2 fb = __half22float2(*(half2*)&v.y);
    return make_float4(fa.x, fa.y, fb.x, fb.y);
}

// ---------------- CSR build ----------------
__global__ void cnt_init_kernel() {
    int i = blockIdx.x * blockDim.x + threadIdx.x;
    if (i < NN) g_cnt[i] = 0;
}
__global__ void cnt_accum_kernel(const int* __restrict__ ei) {
    int e = blockIdx.x * blockDim.x + threadIdx.x;
    if (e < NE) atomicAdd(&g_cnt[ei[NE + e]], 1);
}
__global__ void scan1_kernel() {      // 98 blocks x 1024
    __shared__ int s[1024];
    int t = threadIdx.x;
    int i = blockIdx.x * 1024 + t;
    int x = (i < NN) ? g_cnt[i] : 0;
    s[t] = x;
    __syncthreads();
    #pragma unroll
    for (int off = 1; off < 1024; off <<= 1) {
        int v = (t >= off) ? s[t - off] : 0;
        __syncthreads();
        s[t] += v;
        __syncthreads();
    }
    if (i < NN) g_rp[i] = s[t] - x;
    if (t == 1023) g_bsum[blockIdx.x] = s[1023];
}
__global__ void scan2_kernel(int nblk) {
    __shared__ int s[128];
    int t = threadIdx.x;
    int v = (t < nblk) ? g_bsum[t] : 0;
    s[t] = v;
    __syncthreads();
    #pragma unroll
    for (int off = 1; off < 128; off <<= 1) {
        int u = (t >= off) ? s[t - off] : 0;
        __syncthreads();
        s[t] += u;
        __syncthreads();
    }
    if (t < nblk) g_boff[t] = s[t] - v;
}
__global__ void fin_kernel() {
    int i = blockIdx.x * blockDim.x + threadIdx.x;
    if (i >= NN) return;
    int rp = g_rp[i] + g_boff[i >> 10];
    g_rp[i] = rp;
    g_cur[i] = rp;
    g_deg[i] = rsqrtf(1.0f + (float)g_cnt[i]);
    if (i == 0) g_rp[NN] = NE;
}
__global__ void scatter_kernel(const int* __restrict__ ei) {
    int e = blockIdx.x * blockDim.x + threadIdx.x;
    if (e >= NE) return;
    int c = ei[NE + e];
    int slot = atomicAdd(&g_cur[c], 1);
    g_csr[slot] = ei[e];
}

// -- aggregation (fp16 gather) + residual combine + fp16 round, warp/node --
__global__ void agg_kernel(const __half* __restrict__ src) {
    int gid  = blockIdx.x * blockDim.x + threadIdx.x;
    int node = gid >> 5;
    if (node >= NN) return;
    int lane = gid & 31;
    const uint2* s2 = (const uint2*)src;      // 4 halves per uint2, 32 per row
    float dn = g_deg[node];
    float4 acc = h4_to_f4(s2[(size_t)node * 32 + lane]);
    float w0 = dn * dn;
    acc.x *= w0; acc.y *= w0; acc.z *= w0; acc.w *= w0;
    int j   = g_rp[node];
    int end = g_rp[node + 1];
    for (; j + 7 < end; j += 8) {
        int   si[8];
        float qi[8];
        uint2 vi[8];
        #pragma unroll
        for (int u = 0; u < 8; u++) si[u] = g_csr[j + u];
        #pragma unroll
        for (int u = 0; u < 8; u++) qi[u] = dn * g_deg[si[u]];
        #pragma unroll
        for (int u = 0; u < 8; u++) vi[u] = s2[(size_t)si[u] * 32 + lane];
        #pragma unroll
        for (int u = 0; u < 8; u++) {
            float4 f = h4_to_f4(vi[u]);
            acc.x += qi[u] * f.x;
            acc.y += qi[u] * f.y;
            acc.z += qi[u] * f.z;
            acc.w += qi[u] * f.w;
        }
    }
    for (; j < end; j++) {
        int sa = g_csr[j];
        float wa = dn * g_deg[sa];
        float4 f = h4_to_f4(s2[(size_t)sa * 32 + lane]);
        acc.x += wa * f.x; acc.y += wa * f.y;
        acc.z += wa * f.z; acc.w += wa * f.w;
    }
    float4 h0v = h4_to_f4(((const uint2*)g_h0h)[(size_t)node * 32 + lane]);
    float cx = 0.9f * acc.x + 0.1f * h0v.x;
    float cy = 0.9f * acc.y + 0.1f * h0v.y;
    float cz = 0.9f * acc.z + 0.1f * h0v.z;
    float cw = 0.9f * acc.w + 0.1f * h0v.w;
    half2* ph = (half2*)(g_comb + (size_t)node * HD) + lane * 2;
    ph[0] = __halves2half2(__float2half_rn(cx), __float2half_rn(cy));
    ph[1] = __halves2half2(__float2half_rn(cz), __float2half_rn(cw));
}

// ---------------- weight transpose + fp16 round ----------------
__global__ void prep_weights(const float* __restrict__ w1,
                             const float* __restrict__ cw,
                             const float* __restrict__ w2) {
    int i = blockIdx.x * blockDim.x + threadIdx.x;
    const int N1 = HD * DIN;
    const int N2 = 2 * HD * HD;
    const int N3 = DOUT * HD;
    if (i < N1) {
        int n = i / DIN, k = i % DIN;
        g_w1t[i] = __float2half_rn(w1[(size_t)k * HD + n]);
    } else if (i < N1 + N2) {
        int j = i - N1;
        int l = j / (HD * HD), r = j % (HD * HD);
        int n = r / HD, k = r % HD;
        g_cwt[j] = __float2half_rn(cw[(size_t)l * HD * HD + (size_t)k * HD + n]);
    } else if (i < N1 + N2 + N3) {
        int j = i - N1 - N2;
        int n = j / HD, k = j % HD;
        g_w2t[j] = __float2half_rn(w2[(size_t)k * DOUT + n]);
    }
}

// ======== shared GEMM pieces (BM=128, BK=32, 8 warps, 2 CTAs/SM) ========
#define BKP 40
#define AB_BYTES (128 * BKP * 2)

template<int MF, int NF, int NKS, int ABB, int BBB, int BKPB>
__device__ __forceinline__ void gemm_compute_1t(
    uint32_t uA, uint32_t uB,
    int b, int wm, int wn, int a_r, int a_kc, int b_r, int b_kc,
    float (*acc)[NF][4])
{
    #pragma unroll
    for (int ks = 0; ks < NKS; ks++) {
        uint32_t ah[MF][4];
        #pragma unroll
        for (int mf = 0; mf < MF; mf++) {
            uint32_t off = (uint32_t)(wm + mf * 16 + a_r) * BKPB + ks * 32 + a_kc * 16;
            ldsm4(ah[mf], uA + (uint32_t)b * ABB + off);
        }
        uint32_t bh[NF][2];
        #pragma unroll
        for (int nb = 0; nb < NF / 2; nb++) {
            uint32_t off = (uint32_t)(wn + nb * 16 + b_r) * BKPB + ks * 32 + b_kc * 16;
            uint32_t t[4];
            ldsm4(t, uB + (uint32_t)b * BBB + off);
            bh[2 * nb][0] = t[0]; bh[2 * nb][1] = t[1];
            bh[2 * nb + 1][0] = t[2]; bh[2 * nb + 1][1] = t[3];
        }
        #pragma unroll
        for (int mf = 0; mf < MF; mf++)
            #pragma unroll
            for (int nf = 0; nf < NF; nf++)
                mma_f16(acc[mf][nf], ah[mf], bh[nf]);
    }
}

// HALF_OUT: C is __half* (half2 stores); else float* (float2 stores)
template<int MF, int BN, int NF, bool RELU, bool BIAS, bool HALF_OUT>
__device__ __forceinline__ void gemm_epilogue(
    float (*acc)[NF][4], const float* bias, void* Cv,
    int M, int blockM, int wm, int wn, int lane)
{
    #pragma unroll
    for (int mf = 0; mf < MF; mf++) {
        int row0 = blockM + wm + mf * 16 + (lane >> 2);
        #pragma unroll
        for (int nf = 0; nf < NF; nf++) {
            int col = wn + nf * 8 + (lane & 3) * 2;
            float2 v0 = make_float2(acc[mf][nf][0], acc[mf][nf][1]);
            float2 v1 = make_float2(acc[mf][nf][2], acc[mf][nf][3]);
            if (BIAS) {
                float b0 = bias[col], b1 = bias[col + 1];
                v0.x += b0; v0.y += b1;
                v1.x += b0; v1.y += b1;
            }
            if (RELU) {
                v0.x = fmaxf(v0.x, 0.f); v0.y = fmaxf(v0.y, 0.f);
                v1.x = fmaxf(v1.x, 0.f); v1.y = fmaxf(v1.y, 0.f);
            }
            if (HALF_OUT) {
                __half* C = (__half*)Cv;
                if (row0 < M)
                    *(half2*)(C + (size_t)row0 * BN + col) =
                        __halves2half2(__float2half_rn(v0.x), __float2half_rn(v0.y));
                if (row0 + 8 < M)
                    *(half2*)(C + (size_t)(row0 + 8) * BN + col) =
                        __halves2half2(__float2half_rn(v1.x), __float2half_rn(v1.y));
            } else {
                float* C = (float*)Cv;
                if (row0 < M)     *(float2*)(C + (size_t)row0 * BN + col)       = v0;
                if (row0 + 8 < M) *(float2*)(C + (size_t)(row0 + 8) * BN + col) = v1;
            }
        }
    }
}

// ===== fp32-A single-term GEMM: C = fp16(A) @ Bh^T =====
template<int BN, bool RELU, bool BIAS, bool HALF_OUT>
__global__ void __launch_bounds__(256, 2)
mma_gemm_f32_1t(const float* __restrict__ A,
                const __half* __restrict__ Bh,
                const float* __restrict__ bias, void* C,
                int M, int K)
{
    constexpr int BM = 128, BK = 32;
    constexpr int MF = 4;
    constexpr int WN = BN / 4;
    constexpr int NF = WN / 8;
    constexpr int ASZ = BM * BKP;
    constexpr int BBB = BN * BKP * 2;

    extern __shared__ __half smh[];
    __half* Ap = smh;
    const uint32_t sb = smem_to_u32(smh);
    const uint32_t uA = sb;
    const uint32_t uB = sb + 2 * AB_BYTES;

    const int tid  = threadIdx.x;
    const int lane = tid & 31;
    const int wid  = tid >> 5;
    const int wm   = (wid >> 2) * 64;
    const int wn   = (wid & 3) * WN;
    const int blockM = blockIdx.x * BM;

    const int a_r  = lane & 15, a_kc = lane >> 4;
    const int b_r  = (lane & 7) + ((lane >> 4) << 3);
    const int b_kc = (lane >> 3) & 1;

    float acc[MF][NF][4];
    #pragma unroll
    for (int mf = 0; mf < MF; mf++)
        #pragma unroll
        for (int nf = 0; nf < NF; nf++)
            #pragma unroll
            for (int q = 0; q < 4; q++) acc[mf][nf][q] = 0.0f;

    const int nit = K / BK;

    auto fillB = [&](int i, int b) {
        constexpr int CH = BN * 4;
        #pragma unroll
        for (int it = 0; it < (CH + 255) / 256; it++) {
            int id = tid + it * 256;
            if (CH % 256 == 0 || id < CH) {
                int n = id >> 2, c = id & 3;
                uint32_t off = (uint32_t)b * BBB + (uint32_t)n * (BKP * 2) + c * 16;
                cp_async16(uB + off, Bh + (size_t)n * K + i * BK + c * 8);
            }
        }
    };
    float4 aR[4];
    auto loadA = [&](int i) {
        #pragma unroll
        for (int it = 0; it < 4; it++) {
            int id  = tid + it * 256;
            int row = id >> 3, c4 = id & 7;
            int gr  = blockM + row;
            float4 v = make_float4(0.f, 0.f, 0.f, 0.f);
            if (gr < M)
                v = *(const float4*)(A + (size_t)gr * K + i * BK + c4 * 4);
            aR[it] = v;
        }
    };
    auto storeA = [&](int b) {
        #pragma unroll
        for (int it = 0; it < 4; it++) {
            int id  = tid + it * 256;
            int row = id >> 3, c4 = id & 7;
            float4 v = aR[it];
            int off = b * ASZ + row * BKP + c4 * 4;
            ((half2*)(Ap + off))[0] =
                __halves2half2(__float2half_rn(v.x), __float2half_rn(v.y));
            ((half2*)(Ap + off))[1] =
                __halves2half2(__float2half_rn(v.z), __float2half_rn(v.w));
        }
    };

    loadA(0);
    storeA(0);
    fillB(0, 0);
    cp_commit();

    for (int i = 0; i < nit; i++) {
        const int b = i & 1;
        cp_wait<0>();
        __syncthreads();
        if (i + 1 < nit) {
            fillB(i + 1, b ^ 1);
            cp_commit();
            loadA(i + 1);
        }
        gemm_compute_1t<MF, NF, 2, AB_BYTES, BBB, BKP * 2>(
            uA, uB, b, wm, wn, a_r, a_kc, b_r, b_kc, acc);
        if (i + 1 < nit) storeA(b ^ 1);
    }

    gemm_epilogue<MF, BN, NF, RELU, BIAS, HALF_OUT>(acc, bias, C, M, blockM, wm, wn, lane);
}

// ===== fp16-A single-term GEMM (convs): pure cp.async both sides =====
template<int BN, bool HALF_OUT>
__global__ void __launch_bounds__(256, 2)
mma_gemm_f16_1t(const __half* __restrict__ Ah,
                const __half* __restrict__ Bh,
                void* C, int M, int K)
{
    constexpr int BM = 128, BK = 32;
    constexpr int MF = 4;
    constexpr int WN = BN / 4;
    constexpr int NF = WN / 8;
    constexpr int BBB = BN * BKP * 2;

    extern __shared__ __half smh[];
    const uint32_t sb = smem_to_u32(smh);
    const uint32_t uA = sb;
    const uint32_t uB = sb + 2 * AB_BYTES;

    const int tid  = threadIdx.x;
    const int lane = tid & 31;
    const int wid  = tid >> 5;
    const int wm   = (wid >> 2) * 64;
    const int wn   = (wid & 3) * WN;
    const int blockM = blockIdx.x * BM;

    const int a_r  = lane & 15, a_kc = lane >> 4;
    const int b_r  = (lane & 7) + ((lane >> 4) << 3);
    const int b_kc = (lane >> 3) & 1;

    float acc[MF][NF][4];
    #pragma unroll
    for (int mf = 0; mf < MF; mf++)
        #pragma unroll
        for (int nf = 0; nf < NF; nf++)
            #pragma unroll
            for (int q = 0; q < 4; q++) acc[mf][nf][q] = 0.0f;

    const int nit = K / BK;

    auto fillA = [&](int i, int b) {
        constexpr int CH = BM * 4;
        #pragma unroll
        for (int it = 0; it < CH / 256; it++) {
            int id = tid + it * 256;
            int row = id >> 2, c = id & 3;
            int gr = blockM + row;
            if (gr < M) {
                uint32_t off = (uint32_t)b * AB_BYTES + (uint32_t)row * (BKP * 2) + c * 16;
                cp_async16(uA + off, Ah + (size_t)gr * K + i * BK + c * 8);
            }
        }
    };
    auto fillB = [&](int i, int b) {
        constexpr int CH = BN * 4;
        #pragma unroll
        for (int it = 0; it < (CH + 255) / 256; it++) {
            int id = tid + it * 256;
            if (CH % 256 == 0 || id < CH) {
                int n = id >> 2, c = id & 3;
                uint32_t off = (uint32_t)b * BBB + (uint32_t)n * (BKP * 2) + c * 16;
                cp_async16(uB + off, Bh + (size_t)n * K + i * BK + c * 8);
            }
        }
    };

    fillA(0, 0);
    fillB(0, 0);
    cp_commit();

    for (int i = 0; i < nit; i++) {
        const int b = i & 1;
        cp_wait<0>();
        __syncthreads();
        if (i + 1 < nit) {
            fillA(i + 1, b ^ 1);
            fillB(i + 1, b ^ 1);
            cp_commit();
        }
        gemm_compute_1t<MF, NF, 2, AB_BYTES, BBB, BKP * 2>(
            uA, uB, b, wm, wn, a_r, a_kc, b_r, b_kc, acc);
    }

    gemm_epilogue<MF, BN, NF, false, false, HALF_OUT>(acc, nullptr, C, M, blockM, wm, wn, lane);
}

// ---------------- launch ----------------
extern "C" void kernel_launch(void* const* d_in, const int* in_sizes, int n_in,
                              void* d_out, int out_size)
{
    const float* x  = (const float*)d_in[0];
    const int*   ei = (const int*)  d_in[1];
    const float* w1 = (const float*)d_in[2];
    const float* b1 = (const float*)d_in[3];
    const float* cw = (const float*)d_in[4];
    const float* w2 = (const float*)d_in[5];
    const float* b2 = (const float*)d_in[6];

    float* out    = (float*)d_out;
    float* hout   = out;
    float* logits = out + (size_t)NN * HD;

    __half *p_h0h, *p_hh, *p_comb, *p_w1t, *p_cwt, *p_w2t;
    cudaGetSymbolAddress((void**)&p_h0h,  g_h0h);
    cudaGetSymbolAddress((void**)&p_hh,   g_hh);
    cudaGetSymbolAddress((void**)&p_comb, g_comb);
    cudaGetSymbolAddress((void**)&p_w1t,  g_w1t);
    cudaGetSymbolAddress((void**)&p_cwt,  g_cwt);
    cudaGetSymbolAddress((void**)&p_w2t,  g_w2t);

    const int TPB = 256;
    const int gemm_grid = (NN + 127) / 128;                    // 782
    const int NBLK = (NN + 1023) / 1024;                       // 98
    const int SMEM_G1  = 2 * AB_BYTES + 2 * 128 * BKP * 2;     // 40960 B
    const int SMEM_CV  = 2 * AB_BYTES + 2 * 128 * BKP * 2;     // 40960 B
    const int SMEM_LG  = 2 * AB_BYTES + 2 * 64 * BKP * 2;      // 30720 B

    cudaFuncSetAttribute(mma_gemm_f32_1t<128, true, true, true>,
                         cudaFuncAttributeMaxDynamicSharedMemorySize, SMEM_G1);
    cudaFuncSetAttribute(mma_gemm_f16_1t<128, true>,
                         cudaFuncAttributeMaxDynamicSharedMemorySize, SMEM_CV);
    cudaFuncSetAttribute(mma_gemm_f16_1t<128, false>,
                         cudaFuncAttributeMaxDynamicSharedMemorySize, SMEM_CV);
    cudaFuncSetAttribute(mma_gemm_f32_1t<64, false, true, false>,
                         cudaFuncAttributeMaxDynamicSharedMemorySize, SMEM_LG);

    // launches 1-3, then gemm1 as launch #4 (profiler capture slot)
    cnt_init_kernel <<<(NN + TPB - 1) / TPB, TPB>>>();
    cnt_accum_kernel<<<(NE + TPB - 1) / TPB, TPB>>>(ei);
    prep_weights    <<<(HD*DIN + 2*HD*HD + DOUT*HD + TPB - 1) / TPB, TPB>>>(w1, cw, w2);

    // h0 = relu(fp16(x) @ fp16(w1) + b1) -> fp16   [launch #4 -> profiled]
    mma_gemm_f32_1t<128, true, true, true><<<gemm_grid, 256, SMEM_G1>>>(
        x, p_w1t, b1, p_h0h, NN, DIN);

    // rest of CSR build
    scan1_kernel    <<<NBLK, 1024>>>();
    scan2_kernel    <<<1, 128>>>(NBLK);
    fin_kernel      <<<(NN + TPB - 1) / TPB, TPB>>>();
    scatter_kernel  <<<(NE + TPB - 1) / TPB, TPB>>>(ei);

    // ---- layer 1: agg(h0 fp16) -> comb; h = comb @ cw0 -> fp16 ----
    agg_kernel<<<(NN * 32 + TPB - 1) / TPB, TPB>>>(p_h0h);
    mma_gemm_f16_1t<128, true><<<gemm_grid, 256, SMEM_CV>>>(
        p_comb, p_cwt, p_hh, NN, HD);

    // ---- layer 2: agg(h fp16) -> comb; hout = comb @ cw1 -> fp32 (d_out) ----
    agg_kernel<<<(NN * 32 + TPB - 1) / TPB, TPB>>>(p_hh);
    mma_gemm_f16_1t<128, false><<<gemm_grid, 256, SMEM_CV>>>(
        p_comb, p_cwt + HD * HD, hout, NN, HD);

    // logits = hout @ w2 + b2
    mma_gemm_f32_1t<64, false, true, false><<<gemm_grid, 256, SMEM_LG>>>(
        hout, p_w2t, b2, logits, NN, HD);
}

// round 17
// speedup vs baseline: 1.5359x; 1.0513x over previous
#include <cuda_runtime.h>
#include <cuda_fp16.h>
#include <cstdint>

#define NN   100000
#define NE   1600000
#define DIN  512
#define HD   128
#define DOUT 64

// ---------------- scratch (device globals: allocation-free) ----------------
__device__ float  g_deg[NN];                    // dinv
__device__ __half g_h0h[(size_t)NN * HD];       // h0, fp16 (gather source + residual)
__device__ __half g_hh [(size_t)NN * HD];       // h (layer-1 out), fp16 (gather source)
__device__ __half g_comb[(size_t)NN * HD];      // combined residual input, fp16
// CSR build
__device__ int g_cnt[NN];
__device__ int g_rp [NN + 1];
__device__ int g_cur[NN];
__device__ int g_csr[NE];
__device__ int g_bsum[128], g_boff[128];
// K-major fp16 weights: [N][K]
__device__ __half g_w1t[HD * DIN];
__device__ __half g_cwt[2 * HD * HD];
__device__ __half g_w2t[DOUT * HD];

// ======================= helpers =====================
__device__ __forceinline__ uint32_t smem_to_u32(const void* p) {
    uint32_t a;
    asm("{ .reg .u64 t; cvta.to.shared.u64 t, %1; cvt.u32.u64 %0, t; }" : "=r"(a) : "l"(p));
    return a;
}
__device__ __forceinline__ void ldsm4(uint32_t* r, uint32_t addr) {
    asm volatile("ldmatrix.sync.aligned.m8n8.x4.shared.b16 {%0,%1,%2,%3}, [%4];"
                 : "=r"(r[0]), "=r"(r[1]), "=r"(r[2]), "=r"(r[3]) : "r"(addr));
}
__device__ __forceinline__ void mma_f16(float* c, const uint32_t* a, const uint32_t* b) {
    asm volatile("mma.sync.aligned.m16n8k16.row.col.f32.f16.f16.f32 "
                 "{%0,%1,%2,%3}, {%4,%5,%6,%7}, {%8,%9}, {%0,%1,%2,%3};"
                 : "+f"(c[0]), "+f"(c[1]), "+f"(c[2]), "+f"(c[3])
                 : "r"(a[0]), "r"(a[1]), "r"(a[2]), "r"(a[3]), "r"(b[0]), "r"(b[1]));
}
__device__ __forceinline__ void cp_async16(uint32_t dst, const void* src) {
    asm volatile("cp.async.cg.shared.global [%0], [%1], 16;"
                 :: "r"(dst), "l"((unsigned long long)__cvta_generic_to_global(src)) : "memory");
}
__device__ __forceinline__ void cp_commit() {
    asm volatile("cp.async.commit_group;" ::: "memory");
}
template<int N> __device__ __forceinline__ void cp_wait() {
    asm volatile("cp.async.wait_group %0;" :: "n"(N) : "memory");
}
__device__ __forceinline__ float4 h4_to_f4(uint2 v) {
    float2 fa = __half22float2(*(half2*)&v.x);
    float2 fb = __half22float2(*(half2*)&v.y);
    return make_float4(fa.x, fa.y, fb.x, fb.y);
}

// ---------------- CSR build ----------------
__global__ void cnt_init_kernel() {
    int i = blockIdx.x * blockDim.x + threadIdx.x;
    if (i < NN) g_cnt[i] = 0;
}
__global__ void cnt_accum_kernel(const int* __restrict__ ei) {
    int e = blockIdx.x * blockDim.x + threadIdx.x;
    if (e < NE) atomicAdd(&g_cnt[ei[NE + e]], 1);
}
__global__ void scan1_kernel() {      // 98 blocks x 1024
    __shared__ int s[1024];
    int t = threadIdx.x;
    int i = blockIdx.x * 1024 + t;
    int x = (i < NN) ? g_cnt[i] : 0;
    s[t] = x;
    __syncthreads();
    #pragma unroll
    for (int off = 1; off < 1024; off <<= 1) {
        int v = (t >= off) ? s[t - off] : 0;
        __syncthreads();
        s[t] += v;
        __syncthreads();
    }
    if (i < NN) g_rp[i] = s[t] - x;
    if (t == 1023) g_bsum[blockIdx.x] = s[1023];
}
__global__ void scan2_kernel(int nblk) {
    __shared__ int s[128];
    int t = threadIdx.x;
    int v = (t < nblk) ? g_bsum[t] : 0;
    s[t] = v;
    __syncthreads();
    #pragma unroll
    for (int off = 1; off < 128; off <<= 1) {
        int u = (t >= off) ? s[t - off] : 0;
        __syncthreads();
        s[t] += u;
        __syncthreads();
    }
    if (t < nblk) g_boff[t] = s[t] - v;
}
__global__ void fin_kernel() {
    int i = blockIdx.x * blockDim.x + threadIdx.x;
    if (i >= NN) return;
    int rp = g_rp[i] + g_boff[i >> 10];
    g_rp[i] = rp;
    g_cur[i] = rp;
    g_deg[i] = rsqrtf(1.0f + (float)g_cnt[i]);
    if (i == 0) g_rp[NN] = NE;
}
__global__ void scatter_kernel(const int* __restrict__ ei) {
    int e = blockIdx.x * blockDim.x + threadIdx.x;
    if (e >= NE) return;
    int c = ei[NE + e];
    int slot = atomicAdd(&g_cur[c], 1);
    g_csr[slot] = ei[e];
}

// -- aggregation (fp16 gather) + residual combine + fp16 round, warp/node --
__global__ void agg_kernel(const __half* __restrict__ src) {
    int gid  = blockIdx.x * blockDim.x + threadIdx.x;
    int node = gid >> 5;
    if (node >= NN) return;
    int lane = gid & 31;
    const uint2* s2 = (const uint2*)src;      // 4 halves per uint2, 32 per row
    float dn = g_deg[node];
    float4 acc = h4_to_f4(s2[(size_t)node * 32 + lane]);
    float w0 = dn * dn;
    acc.x *= w0; acc.y *= w0; acc.z *= w0; acc.w *= w0;
    int j   = g_rp[node];
    int end = g_rp[node + 1];
    for (; j + 7 < end; j += 8) {
        int   si[8];
        float qi[8];
        uint2 vi[8];
        #pragma unroll
        for (int u = 0; u < 8; u++) si[u] = g_csr[j + u];
        #pragma unroll
        for (int u = 0; u < 8; u++) qi[u] = dn * g_deg[si[u]];
        #pragma unroll
        for (int u = 0; u < 8; u++) vi[u] = s2[(size_t)si[u] * 32 + lane];
        #pragma unroll
        for (int u = 0; u < 8; u++) {
            float4 f = h4_to_f4(vi[u]);
            acc.x += qi[u] * f.x;
            acc.y += qi[u] * f.y;
            acc.z += qi[u] * f.z;
            acc.w += qi[u] * f.w;
        }
    }
    for (; j < end; j++) {
        int sa = g_csr[j];
        float wa = dn * g_deg[sa];
        float4 f = h4_to_f4(s2[(size_t)sa * 32 + lane]);
        acc.x += wa * f.x; acc.y += wa * f.y;
        acc.z += wa * f.z; acc.w += wa * f.w;
    }
    float4 h0v = h4_to_f4(((const uint2*)g_h0h)[(size_t)node * 32 + lane]);
    float cx = 0.9f * acc.x + 0.1f * h0v.x;
    float cy = 0.9f * acc.y + 0.1f * h0v.y;
    float cz = 0.9f * acc.z + 0.1f * h0v.z;
    float cw = 0.9f * acc.w + 0.1f * h0v.w;
    half2* ph = (half2*)(g_comb + (size_t)node * HD) + lane * 2;
    ph[0] = __halves2half2(__float2half_rn(cx), __float2half_rn(cy));
    ph[1] = __halves2half2(__float2half_rn(cz), __float2half_rn(cw));
}

// ---------------- weight transpose + fp16 round ----------------
__global__ void prep_weights(const float* __restrict__ w1,
                             const float* __restrict__ cw,
                             const float* __restrict__ w2) {
    int i = blockIdx.x * blockDim.x + threadIdx.x;
    const int N1 = HD * DIN;
    const int N2 = 2 * HD * HD;
    const int N3 = DOUT * HD;
    if (i < N1) {
        int n = i / DIN, k = i % DIN;
        g_w1t[i] = __float2half_rn(w1[(size_t)k * HD + n]);
    } else if (i < N1 + N2) {
        int j = i - N1;
        int l = j / (HD * HD), r = j % (HD * HD);
        int n = r / HD, k = r % HD;
        g_cwt[j] = __float2half_rn(cw[(size_t)l * HD * HD + (size_t)k * HD + n]);
    } else if (i < N1 + N2 + N3) {
        int j = i - N1 - N2;
        int n = j / HD, k = j % HD;
        g_w2t[j] = __float2half_rn(w2[(size_t)k * DOUT + n]);
    }
}

// ======== shared GEMM pieces (BM=128, BK=32, 8 warps, 2 CTAs/SM) ========
#define BKP 40
#define AB_BYTES (128 * BKP * 2)

template<int MF, int NF, int NKS, int ABB, int BBB, int BKPB>
__device__ __forceinline__ void gemm_compute_1t(
    uint32_t uA, uint32_t uB,
    int b, int wm, int wn, int a_r, int a_kc, int b_r, int b_kc,
    float (*acc)[NF][4])
{
    #pragma unroll
    for (int ks = 0; ks < NKS; ks++) {
        uint32_t ah[MF][4];
        #pragma unroll
        for (int mf = 0; mf < MF; mf++) {
            uint32_t off = (uint32_t)(wm + mf * 16 + a_r) * BKPB + ks * 32 + a_kc * 16;
            ldsm4(ah[mf], uA + (uint32_t)b * ABB + off);
        }
        uint32_t bh[NF][2];
        #pragma unroll
        for (int nb = 0; nb < NF / 2; nb++) {
            uint32_t off = (uint32_t)(wn + nb * 16 + b_r) * BKPB + ks * 32 + b_kc * 16;
            uint32_t t[4];
            ldsm4(t, uB + (uint32_t)b * BBB + off);
            bh[2 * nb][0] = t[0]; bh[2 * nb][1] = t[1];
            bh[2 * nb + 1][0] = t[2]; bh[2 * nb + 1][1] = t[3];
        }
        #pragma unroll
        for (int mf = 0; mf < MF; mf++)
            #pragma unroll
            for (int nf = 0; nf < NF; nf++)
                mma_f16(acc[mf][nf], ah[mf], bh[nf]);
    }
}

// HALF_OUT: C is __half* (half2 stores); else float* (float2 stores)
template<int MF, int BN, int NF, bool RELU, bool BIAS, bool HALF_OUT>
__device__ __forceinline__ void gemm_epilogue(
    float (*acc)[NF][4], const float* bias, void* Cv,
    int M, int blockM, int wm, int wn, int lane)
{
    #pragma unroll
    for (int mf = 0; mf < MF; mf++) {
        int row0 = blockM + wm + mf * 16 + (lane >> 2);
        #pragma unroll
        for (int nf = 0; nf < NF; nf++) {
            int col = wn + nf * 8 + (lane & 3) * 2;
            float2 v0 = make_float2(acc[mf][nf][0], acc[mf][nf][1]);
            float2 v1 = make_float2(acc[mf][nf][2], acc[mf][nf][3]);
            if (BIAS) {
                float b0 = bias[col], b1 = bias[col + 1];
                v0.x += b0; v0.y += b1;
                v1.x += b0; v1.y += b1;
            }
            if (RELU) {
                v0.x = fmaxf(v0.x, 0.f); v0.y = fmaxf(v0.y, 0.f);
                v1.x = fmaxf(v1.x, 0.f); v1.y = fmaxf(v1.y, 0.f);
            }
            if (HALF_OUT) {
                __half* C = (__half*)Cv;
                if (row0 < M)
                    *(half2*)(C + (size_t)row0 * BN + col) =
                        __halves2half2(__float2half_rn(v0.x), __float2half_rn(v0.y));
                if (row0 + 8 < M)
                    *(half2*)(C + (size_t)(row0 + 8) * BN + col) =
                        __halves2half2(__float2half_rn(v1.x), __float2half_rn(v1.y));
            } else {
                float* C = (float*)Cv;
                if (row0 < M)     *(float2*)(C + (size_t)row0 * BN + col)       = v0;
                if (row0 + 8 < M) *(float2*)(C + (size_t)(row0 + 8) * BN + col) = v1;
            }
        }
    }
}

// ===== fp32-A single-term GEMM: C = fp16(A) @ Bh^T =====
template<int BN, bool RELU, bool BIAS, bool HALF_OUT>
__global__ void __launch_bounds__(256, 2)
mma_gemm_f32_1t(const float* __restrict__ A,
                const __half* __restrict__ Bh,
                const float* __restrict__ bias, void* C,
                int M, int K)
{
    constexpr int BM = 128, BK = 32;
    constexpr int MF = 4;
    constexpr int WN = BN / 4;
    constexpr int NF = WN / 8;
    constexpr int ASZ = BM * BKP;
    constexpr int BBB = BN * BKP * 2;

    extern __shared__ __half smh[];
    __half* Ap = smh;
    const uint32_t sb = smem_to_u32(smh);
    const uint32_t uA = sb;
    const uint32_t uB = sb + 2 * AB_BYTES;

    const int tid  = threadIdx.x;
    const int lane = tid & 31;
    const int wid  = tid >> 5;
    const int wm   = (wid >> 2) * 64;
    const int wn   = (wid & 3) * WN;
    const int blockM = blockIdx.x * BM;

    const int a_r  = lane & 15, a_kc = lane >> 4;
    const int b_r  = (lane & 7) + ((lane >> 4) << 3);
    const int b_kc = (lane >> 3) & 1;

    float acc[MF][NF][4];
    #pragma unroll
    for (int mf = 0; mf < MF; mf++)
        #pragma unroll
        for (int nf = 0; nf < NF; nf++)
            #pragma unroll
            for (int q = 0; q < 4; q++) acc[mf][nf][q] = 0.0f;

    const int nit = K / BK;

    auto fillB = [&](int i, int b) {
        constexpr int CH = BN * 4;
        #pragma unroll
        for (int it = 0; it < (CH + 255) / 256; it++) {
            int id = tid + it * 256;
            if (CH % 256 == 0 || id < CH) {
                int n = id >> 2, c = id & 3;
                uint32_t off = (uint32_t)b * BBB + (uint32_t)n * (BKP * 2) + c * 16;
                cp_async16(uB + off, Bh + (size_t)n * K + i * BK + c * 8);
            }
        }
    };
    float4 aR[4];
    auto loadA = [&](int i) {
        #pragma unroll
        for (int it = 0; it < 4; it++) {
            int id  = tid + it * 256;
            int row = id >> 3, c4 = id & 7;
            int gr  = blockM + row;
            float4 v = make_float4(0.f, 0.f, 0.f, 0.f);
            if (gr < M)
                v = *(const float4*)(A + (size_t)gr * K + i * BK + c4 * 4);
            aR[it] = v;
        }
    };
    auto storeA = [&](int b) {
        #pragma unroll
        for (int it = 0; it < 4; it++) {
            int id  = tid + it * 256;
            int row = id >> 3, c4 = id & 7;
            float4 v = aR[it];
            int off = b * ASZ + row * BKP + c4 * 4;
            ((half2*)(Ap + off))[0] =
                __halves2half2(__float2half_rn(v.x), __float2half_rn(v.y));
            ((half2*)(Ap + off))[1] =
                __halves2half2(__float2half_rn(v.z), __float2half_rn(v.w));
        }
    };

    loadA(0);
    storeA(0);
    fillB(0, 0);
    cp_commit();

    for (int i = 0; i < nit; i++) {
        const int b = i & 1;
        cp_wait<0>();
        __syncthreads();
        if (i + 1 < nit) {
            fillB(i + 1, b ^ 1);
            cp_commit();
            loadA(i + 1);
        }
        gemm_compute_1t<MF, NF, 2, AB_BYTES, BBB, BKP * 2>(
            uA, uB, b, wm, wn, a_r, a_kc, b_r, b_kc, acc);
        if (i + 1 < nit) storeA(b ^ 1);
    }

    gemm_epilogue<MF, BN, NF, RELU, BIAS, HALF_OUT>(acc, bias, C, M, blockM, wm, wn, lane);
}

// ===== fp16-A single-term GEMM (convs): pure cp.async both sides =====
template<int BN, bool HALF_OUT>
__global__ void __launch_bounds__(256, 2)
mma_gemm_f16_1t(const __half* __restrict__ Ah,
                const __half* __restrict__ Bh,
                void* C, int M, int K)
{
    constexpr int BM = 128, BK = 32;
    constexpr int MF = 4;
    constexpr int WN = BN / 4;
    constexpr int NF = WN / 8;
    constexpr int BBB = BN * BKP * 2;

    extern __shared__ __half smh[];
    const uint32_t sb = smem_to_u32(smh);
    const uint32_t uA = sb;
    const uint32_t uB = sb + 2 * AB_BYTES;

    const int tid  = threadIdx.x;
    const int lane = tid & 31;
    const int wid  = tid >> 5;
    const int wm   = (wid >> 2) * 64;
    const int wn   = (wid & 3) * WN;
    const int blockM = blockIdx.x * BM;

    const int a_r  = lane & 15, a_kc = lane >> 4;
    const int b_r  = (lane & 7) + ((lane >> 4) << 3);
    const int b_kc = (lane >> 3) & 1;

    float acc[MF][NF][4];
    #pragma unroll
    for (int mf = 0; mf < MF; mf++)
        #pragma unroll
        for (int nf = 0; nf < NF; nf++)
            #pragma unroll
            for (int q = 0; q < 4; q++) acc[mf][nf][q] = 0.0f;

    const int nit = K / BK;

    auto fillA = [&](int i, int b) {
        constexpr int CH = BM * 4;
        #pragma unroll
        for (int it = 0; it < CH / 256; it++) {
            int id = tid + it * 256;
            int row = id >> 2, c = id & 3;
            int gr = blockM + row;
            if (gr < M) {
                uint32_t off = (uint32_t)b * AB_BYTES + (uint32_t)row * (BKP * 2) + c * 16;
                cp_async16(uA + off, Ah + (size_t)gr * K + i * BK + c * 8);
            }
        }
    };
    auto fillB = [&](int i, int b) {
        constexpr int CH = BN * 4;
        #pragma unroll
        for (int it = 0; it < (CH + 255) / 256; it++) {
            int id = tid + it * 256;
            if (CH % 256 == 0 || id < CH) {
                int n = id >> 2, c = id & 3;
                uint32_t off = (uint32_t)b * BBB + (uint32_t)n * (BKP * 2) + c * 16;
                cp_async16(uB + off, Bh + (size_t)n * K + i * BK + c * 8);
            }
        }
    };

    fillA(0, 0);
    fillB(0, 0);
    cp_commit();

    for (int i = 0; i < nit; i++) {
        const int b = i & 1;
        cp_wait<0>();
        __syncthreads();
        if (i + 1 < nit) {
            fillA(i + 1, b ^ 1);
            fillB(i + 1, b ^ 1);
            cp_commit();
        }
        gemm_compute_1t<MF, NF, 2, AB_BYTES, BBB, BKP * 2>(
            uA, uB, b, wm, wn, a_r, a_kc, b_r, b_kc, acc);
    }

    gemm_epilogue<MF, BN, NF, false, false, HALF_OUT>(acc, nullptr, C, M, blockM, wm, wn, lane);
}

// ---------------- launch ----------------
extern "C" void kernel_launch(void* const* d_in, const int* in_sizes, int n_in,
                              void* d_out, int out_size)
{
    const float* x  = (const float*)d_in[0];
    const int*   ei = (const int*)  d_in[1];
    const float* w1 = (const float*)d_in[2];
    const float* b1 = (const float*)d_in[3];
    const float* cw = (const float*)d_in[4];
    const float* w2 = (const float*)d_in[5];
    const float* b2 = (const float*)d_in[6];

    float* out    = (float*)d_out;
    float* hout   = out;
    float* logits = out + (size_t)NN * HD;

    __half *p_h0h, *p_hh, *p_comb, *p_w1t, *p_cwt, *p_w2t;
    cudaGetSymbolAddress((void**)&p_h0h,  g_h0h);
    cudaGetSymbolAddress((void**)&p_hh,   g_hh);
    cudaGetSymbolAddress((void**)&p_comb, g_comb);
    cudaGetSymbolAddress((void**)&p_w1t,  g_w1t);
    cudaGetSymbolAddress((void**)&p_cwt,  g_cwt);
    cudaGetSymbolAddress((void**)&p_w2t,  g_w2t);

    // side stream + fork/join events for CSR-build || gemm1 overlap.
    // Created once (static); identical launch sequence every call.
    static cudaStream_t s_side = nullptr;
    static cudaEvent_t  ev_fork = nullptr, ev_join = nullptr;
    if (!s_side) {
        cudaStreamCreateWithFlags(&s_side, cudaStreamNonBlocking);
        cudaEventCreateWithFlags(&ev_fork, cudaEventDisableTiming);
        cudaEventCreateWithFlags(&ev_join, cudaEventDisableTiming);
    }

    const int TPB = 256;
    const int gemm_grid = (NN + 127) / 128;                    // 782
    const int NBLK = (NN + 1023) / 1024;                       // 98
    const int SMEM_G1  = 2 * AB_BYTES + 2 * 128 * BKP * 2;     // 40960 B
    const int SMEM_CV  = 2 * AB_BYTES + 2 * 128 * BKP * 2;     // 40960 B
    const int SMEM_LG  = 2 * AB_BYTES + 2 * 64 * BKP * 2;      // 30720 B

    cudaFuncSetAttribute(mma_gemm_f32_1t<128, true, true, true>,
                         cudaFuncAttributeMaxDynamicSharedMemorySize, SMEM_G1);
    cudaFuncSetAttribute(mma_gemm_f16_1t<128, true>,
                         cudaFuncAttributeMaxDynamicSharedMemorySize, SMEM_CV);
    cudaFuncSetAttribute(mma_gemm_f16_1t<128, false>,
                         cudaFuncAttributeMaxDynamicSharedMemorySize, SMEM_CV);
    cudaFuncSetAttribute(mma_gemm_f32_1t<64, false, true, false>,
                         cudaFuncAttributeMaxDynamicSharedMemorySize, SMEM_LG);

    // fork: side stream joins the capture graph via this event
    cudaEventRecord(ev_fork, 0);
    cudaStreamWaitEvent(s_side, ev_fork, 0);

    // launch #1 (main): weight prep
    prep_weights<<<(HD*DIN + 2*HD*HD + DOUT*HD + TPB - 1) / TPB, TPB>>>(w1, cw, w2);
    // launches #2-3 (side): CSR count
    cnt_init_kernel <<<(NN + TPB - 1) / TPB, TPB, 0, s_side>>>();
    cnt_accum_kernel<<<(NE + TPB - 1) / TPB, TPB, 0, s_side>>>(ei);
    // launch #4 (main, profiler slot): h0 = relu(fp16(x) @ fp16(w1) + b1) -> fp16
    mma_gemm_f32_1t<128, true, true, true><<<gemm_grid, 256, SMEM_G1>>>(
        x, p_w1t, b1, p_h0h, NN, DIN);
    // launches #5-8 (side): rest of CSR build, overlapping gemm1
    scan1_kernel    <<<NBLK, 1024, 0, s_side>>>();
    scan2_kernel    <<<1, 128, 0, s_side>>>(NBLK);
    fin_kernel      <<<(NN + TPB - 1) / TPB, TPB, 0, s_side>>>();
    scatter_kernel  <<<(NE + TPB - 1) / TPB, TPB, 0, s_side>>>(ei);
    cudaEventRecord(ev_join, s_side);

    // join: aggregation needs CSR + deg + h0
    cudaStreamWaitEvent(0, ev_join, 0);

    // ---- layer 1: agg(h0 fp16) -> comb; h = comb @ cw0 -> fp16 ----
    agg_kernel<<<(NN * 32 + TPB - 1) / TPB, TPB>>>(p_h0h);
    mma_gemm_f16_1t<128, true><<<gemm_grid, 256, SMEM_CV>>>(
        p_comb, p_cwt, p_hh, NN, HD);

    // ---- layer 2: agg(h fp16) -> comb; hout = comb @ cw1 -> fp32 (d_out) ----
    agg_kernel<<<(NN * 32 + TPB - 1) / TPB, TPB>>>(p_hh);
    mma_gemm_f16_1t<128, false><<<gemm_grid, 256, SMEM_CV>>>(
        p_comb, p_cwt + HD * HD, hout, NN, HD);

    // logits = hout @ w2 + b2
    mma_gemm_f32_1t<64, false, true, false><<<gemm_grid, 256, SMEM_LG>>>(
        hout, p_w2t, b2, logits, NN, HD);
}